// round 1
// baseline (speedup 1.0000x reference)
#include <cuda_runtime.h>
#include <cuda_bf16.h>

#define NM 3
#define NB 64
#define ND 512
#define NDH 128
#define HISTF 5.0f
#define SMOOTHF 0.8f
#define INV_SCALE 0.04419417382415922f  // 1/sqrt(512)

// ---------------- scratch (static device globals; no allocation) ----------------
__device__ float g_proj[NM * NB * ND];
__device__ float g_h[NM * NB * NDH];
__device__ float g_wf[NM * NB * ND];
__device__ float g_rowsum[NM * NB];
__device__ float g_Hsum[NM * ND * ND];
__device__ float g_att1[NM * NB * ND];
__device__ float g_att2[NM * NB * ND];

// ---------------- reduction helpers ----------------
__device__ __forceinline__ float warpRedSum(float v) {
#pragma unroll
    for (int o = 16; o; o >>= 1) v += __shfl_xor_sync(0xffffffffu, v, o);
    return v;
}
__device__ __forceinline__ float warpRedMax(float v) {
#pragma unroll
    for (int o = 16; o; o >>= 1) v = fmaxf(v, __shfl_xor_sync(0xffffffffu, v, o));
    return v;
}

// ---------------- K1: proj = relu(LN(x @ W.T + b)) ----------------
__global__ void k_proj(const float* __restrict__ x, const float* __restrict__ W,
                       const float* __restrict__ pb, const float* __restrict__ lg,
                       const float* __restrict__ lb) {
    int i = blockIdx.x >> 6, b = blockIdx.x & 63;
    int d = threadIdx.x, lane = d & 31, wid = d >> 5;
    __shared__ float xs[ND];
    __shared__ float sred[16];
    __shared__ float sb;
    xs[d] = x[((i << 6) + b) * ND + d];
    __syncthreads();
    const float4* Wr = (const float4*)(W + ((size_t)(i * ND + d)) * ND);
    const float4* xr = (const float4*)xs;
    float acc = 0.f;
#pragma unroll 16
    for (int k = 0; k < ND / 4; k++) {
        float4 w = Wr[k];
        float4 xv = xr[k];
        acc = fmaf(w.x, xv.x, fmaf(w.y, xv.y, fmaf(w.z, xv.z, fmaf(w.w, xv.w, acc))));
    }
    acc += pb[i * ND + d];
    // mean
    float s = warpRedSum(acc);
    if (lane == 0) sred[wid] = s;
    __syncthreads();
    if (wid == 0) {
        float t = (lane < 16) ? sred[lane] : 0.f;
        t = warpRedSum(t);
        if (lane == 0) sb = t;
    }
    __syncthreads();
    float mu = sb * (1.0f / ND);
    __syncthreads();
    // var
    float dv = acc - mu;
    s = warpRedSum(dv * dv);
    if (lane == 0) sred[wid] = s;
    __syncthreads();
    if (wid == 0) {
        float t = (lane < 16) ? sred[lane] : 0.f;
        t = warpRedSum(t);
        if (lane == 0) sb = t;
    }
    __syncthreads();
    float var = sb * (1.0f / ND);
    float y = dv * rsqrtf(var + 1e-5f) * lg[i * ND + d] + lb[i * ND + d];
    g_proj[((i << 6) + b) * ND + d] = fmaxf(y, 0.f);
}

// ---------------- K2: h = relu(proj @ W1.T + b1) ----------------
__global__ void k_imp1(const float* __restrict__ W1, const float* __restrict__ b1) {
    int i = blockIdx.x >> 6, b = blockIdx.x & 63;
    int d = threadIdx.x;  // 128 threads
    __shared__ float ps[ND];
    const float* prow = g_proj + ((i << 6) + b) * ND;
#pragma unroll
    for (int t = 0; t < 4; t++) ps[d + t * NDH] = prow[d + t * NDH];
    __syncthreads();
    const float4* Wr = (const float4*)(W1 + ((size_t)(i * NDH + d)) * ND);
    const float4* xr = (const float4*)ps;
    float acc = 0.f;
#pragma unroll 16
    for (int k = 0; k < ND / 4; k++) {
        float4 w = Wr[k];
        float4 xv = xr[k];
        acc = fmaf(w.x, xv.x, fmaf(w.y, xv.y, fmaf(w.z, xv.z, fmaf(w.w, xv.w, acc))));
    }
    acc += b1[i * NDH + d];
    g_h[((i << 6) + b) * NDH + d] = fmaxf(acc, 0.f);
}

// ---------------- K3: cw = sigmoid(h @ W2.T + b2); wf = proj*cw; rowsum ----------------
__global__ void k_wf(const float* __restrict__ W2, const float* __restrict__ b2) {
    int i = blockIdx.x >> 6, b = blockIdx.x & 63;
    int d = threadIdx.x, lane = d & 31, wid = d >> 5;
    __shared__ float hs[NDH];
    __shared__ float sred[16];
    if (d < NDH) hs[d] = g_h[((i << 6) + b) * NDH + d];
    __syncthreads();
    const float4* Wr = (const float4*)(W2 + ((size_t)(i * ND + d)) * NDH);
    const float4* xr = (const float4*)hs;
    float acc = 0.f;
#pragma unroll
    for (int k = 0; k < NDH / 4; k++) {
        float4 w = Wr[k];
        float4 xv = xr[k];
        acc = fmaf(w.x, xv.x, fmaf(w.y, xv.y, fmaf(w.z, xv.z, fmaf(w.w, xv.w, acc))));
    }
    acc += b2[i * ND + d];
    float cwv = 1.0f / (1.0f + __expf(-acc));
    float wfv = g_proj[((i << 6) + b) * ND + d] * cwv;
    g_wf[((i << 6) + b) * ND + d] = wfv;
    float s = warpRedSum(wfv);
    if (lane == 0) sred[wid] = s;
    __syncthreads();
    if (wid == 0) {
        float t = (lane < 16) ? sred[lane] : 0.f;
        t = warpRedSum(t);
        if (lane == 0) g_rowsum[(i << 6) + b] = t;
    }
}

// ---------------- K4: pass 1 (hist = 0), also accumulate Hsum ----------------
__global__ void k_pass1(const float* __restrict__ modal_bias,
                        const float* __restrict__ constraint) {
    int i = blockIdx.x >> 9;
    int d = blockIdx.x & 511;
    int e = threadIdx.x, lane = e & 31, wid = e >> 5;
    int j = (i == 0) ? 1 : 0;
    float c = constraint[i];
    float bias = modal_bias[i * NM + j];
    __shared__ float a_s[NB];
    __shared__ float sredM[16], sredX[16], sredY[16];
    __shared__ float sbM, sbS, sbD;
    if (e < NB) a_s[e] = g_wf[((i << 6) + e) * ND + d] * INV_SCALE;
    __syncthreads();
    const float* wfj = g_wf + ((size_t)(j << 6)) * ND;
    const float* rsj = g_rowsum + (j << 6);
    float Hacc = 0.f;
    for (int b = 0; b < NB; b++) {
        float a = a_s[b];
        float v = wfj[b * ND + e];
        float cur = a * v;
        float cl = fminf(fmaxf(cur, -c), c);
        float f = SMOOTHF * cl + (1.f - SMOOTHF) * cur;
        Hacc += f;
        // block max
        float m = warpRedMax(f);
        if (lane == 0) sredM[wid] = m;
        __syncthreads();
        if (wid == 0) {
            float t = (lane < 16) ? sredM[lane] : -3.4e38f;
            t = warpRedMax(t);
            if (lane == 0) sbM = t;
        }
        __syncthreads();
        m = sbM;
        float p = __expf(f - m);
        float ps = warpRedSum(p);
        float pd = warpRedSum(p * v);
        if (lane == 0) { sredX[wid] = ps; sredY[wid] = pd; }
        __syncthreads();
        if (wid == 0) {
            float tx = (lane < 16) ? sredX[lane] : 0.f;
            float ty = (lane < 16) ? sredY[lane] : 0.f;
            tx = warpRedSum(tx);
            ty = warpRedSum(ty);
            if (lane == 0) { sbS = tx; sbD = ty; }
        }
        __syncthreads();
        if (e == 0) g_att1[((i << 6) + b) * ND + d] = sbD / sbS + bias * rsj[b];
    }
    g_Hsum[((size_t)i * ND + d) * ND + e] = Hacc;
}

// ---------------- K5: pass 2 (hist = Hsum/(B*HIST)) ----------------
__global__ void k_pass2(const float* __restrict__ modal_bias,
                        const float* __restrict__ constraint) {
    int i = blockIdx.x >> 9;
    int d = blockIdx.x & 511;
    int e = threadIdx.x, lane = e & 31, wid = e >> 5;
    int j = (i == 2) ? 1 : 2;
    float c = constraint[i];
    float bias = modal_bias[i * NM + j];
    float hist = g_Hsum[((size_t)i * ND + d) * ND + e] * (1.0f / (NB * HISTF));
    __shared__ float a_s[NB];
    __shared__ float sredM[16], sredX[16], sredY[16];
    __shared__ float sbM, sbS, sbD;
    if (e < NB) a_s[e] = g_wf[((i << 6) + e) * ND + d] * INV_SCALE;
    __syncthreads();
    const float* wfj = g_wf + ((size_t)(j << 6)) * ND;
    const float* rsj = g_rowsum + (j << 6);
    for (int b = 0; b < NB; b++) {
        float a = a_s[b];
        float v = wfj[b * ND + e];
        float cur = a * v;
        float cl = fminf(fmaxf(cur - hist, -c), c);
        float f = SMOOTHF * (hist + cl) + (1.f - SMOOTHF) * cur;
        float m = warpRedMax(f);
        if (lane == 0) sredM[wid] = m;
        __syncthreads();
        if (wid == 0) {
            float t = (lane < 16) ? sredM[lane] : -3.4e38f;
            t = warpRedMax(t);
            if (lane == 0) sbM = t;
        }
        __syncthreads();
        m = sbM;
        float p = __expf(f - m);
        float ps = warpRedSum(p);
        float pd = warpRedSum(p * v);
        if (lane == 0) { sredX[wid] = ps; sredY[wid] = pd; }
        __syncthreads();
        if (wid == 0) {
            float tx = (lane < 16) ? sredX[lane] : 0.f;
            float ty = (lane < 16) ? sredY[lane] : 0.f;
            tx = warpRedSum(tx);
            ty = warpRedSum(ty);
            if (lane == 0) { sbS = tx; sbD = ty; }
        }
        __syncthreads();
        if (e == 0) g_att2[((i << 6) + b) * ND + d] = sbD / sbS + bias * rsj[b];
    }
}

// ---------------- K6: fuse + attention weights ----------------
__global__ void k_final(const float* __restrict__ gamma, float* __restrict__ out) {
    int b = blockIdx.x, d = threadIdx.x;
    float acc = 0.f;
#pragma unroll
    for (int i = 0; i < NM; i++) {
        int j1 = (i == 0) ? 1 : 0;
        int j2 = (i == 2) ? 1 : 2;
        float g1 = 1.f / (1.f + __expf(-gamma[i * NM + j1]));
        float g2 = 1.f / (1.f + __expf(-gamma[i * NM + j2]));
        int idx = ((i << 6) + b) * ND + d;
        acc += g_wf[idx] + 0.5f * (g1 * g_att1[idx] + g2 * g_att2[idx]);
    }
    out[b * ND + d] = acc * (1.0f / 3.0f);
    if (b == 0 && d == 0) {
        float sc[NM];
        float mx = -3.4e38f;
#pragma unroll
        for (int i = 0; i < NM; i++) {
            int j1 = (i == 0) ? 1 : 0;
            int j2 = (i == 2) ? 1 : 2;
            float g1 = 1.f / (1.f + __expf(-gamma[i * NM + j1]));
            float g2 = 1.f / (1.f + __expf(-gamma[i * NM + j2]));
            sc[i] = 0.5f * (g1 + g2);
            mx = fmaxf(mx, sc[i]);
        }
        float s = 0.f;
#pragma unroll
        for (int i = 0; i < NM; i++) { sc[i] = __expf(sc[i] - mx); s += sc[i]; }
#pragma unroll
        for (int i = 0; i < NM; i++) out[NB * ND + i] = sc[i] / s;
    }
}

extern "C" void kernel_launch(void* const* d_in, const int* in_sizes, int n_in,
                              void* d_out, int out_size) {
    const float* x          = (const float*)d_in[0];
    const float* proj_W     = (const float*)d_in[1];
    const float* proj_b     = (const float*)d_in[2];
    const float* ln_g       = (const float*)d_in[3];
    const float* ln_b       = (const float*)d_in[4];
    const float* imp_W1     = (const float*)d_in[5];
    const float* imp_b1     = (const float*)d_in[6];
    const float* imp_W2     = (const float*)d_in[7];
    const float* imp_b2     = (const float*)d_in[8];
    const float* gamma      = (const float*)d_in[9];
    const float* modal_bias = (const float*)d_in[10];
    const float* constraint = (const float*)d_in[11];
    float* out = (float*)d_out;

    k_proj<<<NM * NB, ND>>>(x, proj_W, proj_b, ln_g, ln_b);
    k_imp1<<<NM * NB, NDH>>>(imp_W1, imp_b1);
    k_wf<<<NM * NB, ND>>>(imp_W2, imp_b2);
    k_pass1<<<NM * ND, ND>>>(modal_bias, constraint);
    k_pass2<<<NM * ND, ND>>>(modal_bias, constraint);
    k_final<<<NB, ND>>>(gamma, out);
}

// round 2
// speedup vs baseline: 3.3149x; 3.3149x over previous
#include <cuda_runtime.h>
#include <cuda_bf16.h>

#define NM 3
#define NB 64
#define ND 512
#define NDH 128
#define INV_SCALE 0.04419417382415922f   // 1/sqrt(512)
#define INV_HIST_B 0.003125f             // 1/(64*5)

// ---------------- scratch (static device globals; no allocation) ----------------
__device__ float g_Wt [NM * ND * ND];    // proj_W transposed: [i][k][d]
__device__ float g_W1t[NM * ND * NDH];   // imp_W1 transposed: [i][k][dh]
__device__ float g_W2t[NM * NDH * ND];   // imp_W2 transposed: [i][kh][d]
__device__ float g_wf [NM * NB * ND];
__device__ float g_rowsum[NM * NB];
__device__ float g_att1[NM * NB * ND];
__device__ float g_att2[NM * NB * ND];

// ---------------- reduction helpers ----------------
__device__ __forceinline__ float warpRedSum(float v) {
#pragma unroll
    for (int o = 16; o; o >>= 1) v += __shfl_xor_sync(0xffffffffu, v, o);
    return v;
}
__device__ __forceinline__ float warpRedMax(float v) {
#pragma unroll
    for (int o = 16; o; o >>= 1) v = fmaxf(v, __shfl_xor_sync(0xffffffffu, v, o));
    return v;
}

// 4-lane-vector block reduction over 512 threads: results land in sb[0..3]
__device__ __forceinline__ void blockRed4(const float* vals, float (*sred)[16],
                                          float* sb, int lane, int wid) {
#pragma unroll
    for (int q = 0; q < 4; q++) {
        float s = warpRedSum(vals[q]);
        if (lane == 0) sred[q][wid] = s;
    }
    __syncthreads();
    if (wid < 4) {
        float t = (lane < 16) ? sred[wid][lane] : 0.f;
        t = warpRedSum(t);
        if (lane == 0) sb[wid] = t;
    }
    __syncthreads();
}

// ---------------- K0: coalesced transpose of a weight batch ----------------
// src: NM matrices [R][C]; dst: NM matrices [C][R].
__global__ void k_transpose(const float* __restrict__ src, int which, int R, int C) {
    float* dst = (which == 0) ? g_Wt : (which == 1) ? g_W1t : g_W2t;
    __shared__ float tile[32][33];
    int i = blockIdx.z;
    int c0 = blockIdx.x * 32, r0 = blockIdx.y * 32;
    const float* s = src + (size_t)i * R * C;
    float* dd = dst + (size_t)i * R * C;
    int tx = threadIdx.x, ty = threadIdx.y;
#pragma unroll
    for (int rr = ty; rr < 32; rr += 8)
        tile[rr][tx] = s[(size_t)(r0 + rr) * C + c0 + tx];
    __syncthreads();
#pragma unroll
    for (int cc = ty; cc < 32; cc += 8)
        dd[(size_t)(c0 + cc) * R + r0 + tx] = tile[tx][cc];
}

// ---------------- K1: fused stage A ----------------
// proj = relu(LN(x@W.T+b)); h = relu(proj@W1.T+b1); cw = sigmoid(h@W2.T+b2);
// wf = proj*cw; rowsum = sum_d wf.  Block = (i, b-tile of 4), 512 threads (one per d).
__global__ __launch_bounds__(512) void k_stageA(
        const float* __restrict__ x, const float* __restrict__ pb,
        const float* __restrict__ lg, const float* __restrict__ lb,
        const float* __restrict__ b1, const float* __restrict__ b2) {
    int i = blockIdx.x >> 4;
    int b0 = (blockIdx.x & 15) << 2;
    int tid = threadIdx.x, lane = tid & 31, wid = tid >> 5;
    int d = tid;

    __shared__ float xs4[ND * 4];      // interleaved [k][q]
    __shared__ float proj_s[4 * ND];   // [q][d]
    __shared__ float proj_i[ND * 4];   // interleaved [k][q]
    __shared__ float sP[16 * NDH];     // partials [(ks*4+q)][dh]
    __shared__ float h_i[NDH * 4];     // interleaved [kh][q]
    __shared__ float sred[4][16];
    __shared__ float sb[4];

    // stage x (interleaved for broadcast-friendly float4 reads)
#pragma unroll
    for (int q = 0; q < 4; q++)
        xs4[d * 4 + q] = x[((i << 6) + b0 + q) * ND + d];
    __syncthreads();

    // ---- proj GEMM: acc[q] = x[q] . W[d,:] via transposed W (coalesced) ----
    const float* Wt = g_Wt + (size_t)i * ND * ND;
    float acc[4] = {0.f, 0.f, 0.f, 0.f};
#pragma unroll 8
    for (int k = 0; k < ND; k++) {
        float w = Wt[k * ND + d];
        float4 xq = ((const float4*)xs4)[k];
        acc[0] = fmaf(w, xq.x, acc[0]);
        acc[1] = fmaf(w, xq.y, acc[1]);
        acc[2] = fmaf(w, xq.z, acc[2]);
        acc[3] = fmaf(w, xq.w, acc[3]);
    }
    float pbv = pb[i * ND + d];
#pragma unroll
    for (int q = 0; q < 4; q++) acc[q] += pbv;

    // ---- LayerNorm + ReLU ----
    blockRed4(acc, sred, sb, lane, wid);
    float mu[4], dv[4], sq[4];
#pragma unroll
    for (int q = 0; q < 4; q++) { mu[q] = sb[q] * (1.f / ND); dv[q] = acc[q] - mu[q]; sq[q] = dv[q] * dv[q]; }
    blockRed4(sq, sred, sb, lane, wid);
    float lgv = lg[i * ND + d], lbv = lb[i * ND + d];
#pragma unroll
    for (int q = 0; q < 4; q++) {
        float var = sb[q] * (1.f / ND);
        float y = dv[q] * rsqrtf(var + 1e-5f) * lgv + lbv;
        y = fmaxf(y, 0.f);
        proj_s[q * ND + d] = y;
        proj_i[d * 4 + q] = y;
    }
    __syncthreads();

    // ---- imp1: h = relu(proj @ W1.T + b1), k-split by 4 ----
    {
        int dh = tid & 127, ks = tid >> 7;
        const float* W1t = g_W1t + (size_t)i * ND * NDH;
        float a1[4] = {0.f, 0.f, 0.f, 0.f};
        int k0 = ks * 128;
#pragma unroll 8
        for (int k = k0; k < k0 + 128; k++) {
            float w = W1t[k * NDH + dh];
            float4 pq = ((const float4*)proj_i)[k];
            a1[0] = fmaf(w, pq.x, a1[0]);
            a1[1] = fmaf(w, pq.y, a1[1]);
            a1[2] = fmaf(w, pq.z, a1[2]);
            a1[3] = fmaf(w, pq.w, a1[3]);
        }
#pragma unroll
        for (int q = 0; q < 4; q++) sP[(ks * 4 + q) * NDH + dh] = a1[q];
    }
    __syncthreads();
    {
        int dh2 = tid & 127, q2 = tid >> 7;
        float hs = sP[(0 * 4 + q2) * NDH + dh2] + sP[(1 * 4 + q2) * NDH + dh2]
                 + sP[(2 * 4 + q2) * NDH + dh2] + sP[(3 * 4 + q2) * NDH + dh2]
                 + b1[i * NDH + dh2];
        h_i[dh2 * 4 + q2] = fmaxf(hs, 0.f);
    }
    __syncthreads();

    // ---- imp2 + sigmoid + wf + rowsum ----
    const float* W2t = g_W2t + (size_t)i * NDH * ND;
    float a2[4] = {0.f, 0.f, 0.f, 0.f};
#pragma unroll 8
    for (int kh = 0; kh < NDH; kh++) {
        float w = W2t[kh * ND + d];
        float4 hq = ((const float4*)h_i)[kh];
        a2[0] = fmaf(w, hq.x, a2[0]);
        a2[1] = fmaf(w, hq.y, a2[1]);
        a2[2] = fmaf(w, hq.z, a2[2]);
        a2[3] = fmaf(w, hq.w, a2[3]);
    }
    float b2v = b2[i * ND + d];
    float wfv[4];
#pragma unroll
    for (int q = 0; q < 4; q++) {
        float cw = 1.f / (1.f + __expf(-(a2[q] + b2v)));
        wfv[q] = proj_s[q * ND + d] * cw;
        g_wf[((i << 6) + b0 + q) * ND + d] = wfv[q];
    }
    blockRed4(wfv, sred, sb, lane, wid);
    if (tid < 4) g_rowsum[(i << 6) + b0 + tid] = sb[tid];
}

// ---------------- K2: fused pass1 + pass2 (warp-owned rows) ----------------
// Warp owns (i, d) and half the batch. History partial exchanged once via smem.
__global__ __launch_bounds__(256) void k_pass(const float* __restrict__ modal_bias,
                                              const float* __restrict__ constraint) {
    int i = blockIdx.x >> 7;
    int db = (blockIdx.x & 127) << 2;
    int tid = threadIdx.x, lane = tid & 31, wid = tid >> 5;
    int dl = wid >> 1, h = wid & 1;
    int d = db + dl;
    int j1 = (i == 0) ? 1 : 0;
    int j2 = (i == 2) ? 1 : 2;
    float c = constraint[i];
    float bias1 = modal_bias[i * NM + j1];
    float bias2 = modal_bias[i * NM + j2];
    const float* wfi = g_wf + (size_t)i * NB * ND;
    const float* wf1 = g_wf + (size_t)j1 * NB * ND;
    const float* wf2 = g_wf + (size_t)j2 * NB * ND;
    const float* rs1 = g_rowsum + j1 * NB;
    const float* rs2 = g_rowsum + j2 * NB;

    __shared__ float sH[8][ND];

    // a[b] for this warp's 32 batch rows, one per lane
    float a_r = wfi[(h * 32 + lane) * ND + d] * INV_SCALE;

    float Hk[16];
#pragma unroll
    for (int k = 0; k < 16; k++) Hk[k] = 0.f;

    // ---- pass A (hist = 0), pair (i, j1) ----
    for (int bb = 0; bb < 32; bb++) {
        int b = h * 32 + bb;
        float a = __shfl_sync(0xffffffffu, a_r, bb);
        const float* vr = wf1 + b * ND;
        float v[16], f[16];
        float m = -3.4e38f;
#pragma unroll
        for (int k = 0; k < 16; k++) {
            v[k] = vr[k * 32 + lane];
            float cur = a * v[k];
            float cl = fminf(fmaxf(cur, -c), c);
            f[k] = 0.8f * cl + 0.2f * cur;
            m = fmaxf(m, f[k]);
        }
        m = warpRedMax(m);
        float ps = 0.f, pd = 0.f;
#pragma unroll
        for (int k = 0; k < 16; k++) {
            float p = __expf(f[k] - m);
            ps += p;
            pd = fmaf(p, v[k], pd);
            Hk[k] += f[k];
        }
        ps = warpRedSum(ps);
        pd = warpRedSum(pd);
        if (lane == 0)
            g_att1[((i << 6) + b) * ND + d] = pd / ps + bias1 * rs1[b];
    }

    // exchange history partials between the two half-batch warps of this d
#pragma unroll
    for (int k = 0; k < 16; k++) sH[wid][k * 32 + lane] = Hk[k];
    __syncthreads();
#pragma unroll
    for (int k = 0; k < 16; k++)
        Hk[k] = (sH[dl * 2][k * 32 + lane] + sH[dl * 2 + 1][k * 32 + lane]) * INV_HIST_B;

    // ---- pass B (hist from pass A), pair (i, j2) ----
    for (int bb = 0; bb < 32; bb++) {
        int b = h * 32 + bb;
        float a = __shfl_sync(0xffffffffu, a_r, bb);
        const float* vr = wf2 + b * ND;
        float v[16], f[16];
        float m = -3.4e38f;
#pragma unroll
        for (int k = 0; k < 16; k++) {
            v[k] = vr[k * 32 + lane];
            float cur = a * v[k];
            float hist = Hk[k];
            float cl = fminf(fmaxf(cur - hist, -c), c);
            f[k] = 0.8f * (hist + cl) + 0.2f * cur;
            m = fmaxf(m, f[k]);
        }
        m = warpRedMax(m);
        float ps = 0.f, pd = 0.f;
#pragma unroll
        for (int k = 0; k < 16; k++) {
            float p = __expf(f[k] - m);
            ps += p;
            pd = fmaf(p, v[k], pd);
        }
        ps = warpRedSum(ps);
        pd = warpRedSum(pd);
        if (lane == 0)
            g_att2[((i << 6) + b) * ND + d] = pd / ps + bias2 * rs2[b];
    }
}

// ---------------- K3: fuse + attention weights ----------------
__global__ void k_final(const float* __restrict__ gamma, float* __restrict__ out) {
    int b = blockIdx.x, d = threadIdx.x;
    float acc = 0.f;
#pragma unroll
    for (int i = 0; i < NM; i++) {
        int j1 = (i == 0) ? 1 : 0;
        int j2 = (i == 2) ? 1 : 2;
        float g1 = 1.f / (1.f + __expf(-gamma[i * NM + j1]));
        float g2 = 1.f / (1.f + __expf(-gamma[i * NM + j2]));
        int idx = ((i << 6) + b) * ND + d;
        acc += g_wf[idx] + 0.5f * (g1 * g_att1[idx] + g2 * g_att2[idx]);
    }
    out[b * ND + d] = acc * (1.0f / 3.0f);
    if (b == 0 && d == 0) {
        float sc[NM];
        float mx = -3.4e38f;
#pragma unroll
        for (int i = 0; i < NM; i++) {
            int j1 = (i == 0) ? 1 : 0;
            int j2 = (i == 2) ? 1 : 2;
            float g1 = 1.f / (1.f + __expf(-gamma[i * NM + j1]));
            float g2 = 1.f / (1.f + __expf(-gamma[i * NM + j2]));
            sc[i] = 0.5f * (g1 + g2);
            mx = fmaxf(mx, sc[i]);
        }
        float s = 0.f;
#pragma unroll
        for (int i = 0; i < NM; i++) { sc[i] = __expf(sc[i] - mx); s += sc[i]; }
#pragma unroll
        for (int i = 0; i < NM; i++) out[NB * ND + i] = sc[i] / s;
    }
}

extern "C" void kernel_launch(void* const* d_in, const int* in_sizes, int n_in,
                              void* d_out, int out_size) {
    const float* x          = (const float*)d_in[0];
    const float* proj_W     = (const float*)d_in[1];
    const float* proj_b     = (const float*)d_in[2];
    const float* ln_g       = (const float*)d_in[3];
    const float* ln_b       = (const float*)d_in[4];
    const float* imp_W1     = (const float*)d_in[5];
    const float* imp_b1     = (const float*)d_in[6];
    const float* imp_W2     = (const float*)d_in[7];
    const float* imp_b2     = (const float*)d_in[8];
    const float* gamma      = (const float*)d_in[9];
    const float* modal_bias = (const float*)d_in[10];
    const float* constraint = (const float*)d_in[11];
    float* out = (float*)d_out;

    k_transpose<<<dim3(16, 16, NM), dim3(32, 8)>>>(proj_W, 0, ND, ND);   // [d][k]->[k][d]
    k_transpose<<<dim3(16, 4, NM),  dim3(32, 8)>>>(imp_W1, 1, NDH, ND);  // [dh][k]->[k][dh]
    k_transpose<<<dim3(4, 16, NM),  dim3(32, 8)>>>(imp_W2, 2, ND, NDH);  // [d][kh]->[kh][d]
    k_stageA<<<NM * 16, 512>>>(x, proj_b, ln_g, ln_b, imp_b1, imp_b2);
    k_pass<<<NM * ND / 4, 256>>>(modal_bias, constraint);
    k_final<<<NB, ND>>>(gamma, out);
}

// round 3
// speedup vs baseline: 3.6739x; 1.1083x over previous
#include <cuda_runtime.h>
#include <cuda_bf16.h>

#define NM 3
#define NB 64
#define ND 512
#define NDH 128
#define INV_SCALE 0.04419417382415922f   // 1/sqrt(512)
#define INV_HIST_B 0.003125f             // 1/(64*5)
#define LOG2E 1.4426950408889634f
#define SPLITK 8
#define KB (ND / SPLITK)                 // 64 k per gemm block

typedef unsigned long long ull;

// ---------------- scratch (static device globals; no allocation) ----------------
__device__ __align__(16) float g_pp [SPLITK * NM * NB * ND];  // split-k partials
__device__ __align__(16) float g_W1t[NM * ND * NDH];          // imp_W1^T: [i][k][dh]
__device__ __align__(16) float g_W2t[NM * NDH * ND];          // imp_W2^T: [i][kh][d]
__device__ __align__(16) float g_wf [NM * NB * ND];
__device__ float g_rowsum[NM * NB];
__device__ __align__(16) float g_att1[NM * NB * ND];
__device__ __align__(16) float g_att2[NM * NB * ND];

// ---------------- packed f32x2 helpers ----------------
__device__ __forceinline__ ull pk2(float lo, float hi) {
    ull r; asm("mov.b64 %0, {%1, %2};" : "=l"(r) : "f"(lo), "f"(hi)); return r;
}
__device__ __forceinline__ void upk2(ull v, float& lo, float& hi) {
    asm("mov.b64 {%0, %1}, %2;" : "=f"(lo), "=f"(hi) : "l"(v));
}
__device__ __forceinline__ ull mul2(ull a, ull b) {
    ull r; asm("mul.rn.f32x2 %0, %1, %2;" : "=l"(r) : "l"(a), "l"(b)); return r;
}
__device__ __forceinline__ ull add2(ull a, ull b) {
    ull r; asm("add.rn.f32x2 %0, %1, %2;" : "=l"(r) : "l"(a), "l"(b)); return r;
}
__device__ __forceinline__ ull fma2(ull a, ull b, ull c) {
    ull r; asm("fma.rn.f32x2 %0, %1, %2, %3;" : "=l"(r) : "l"(a), "l"(b), "l"(c)); return r;
}
__device__ __forceinline__ float ex2f(float x) {
    float r; asm("ex2.approx.ftz.f32 %0, %1;" : "=f"(r) : "f"(x)); return r;
}

// ---------------- reduction helpers ----------------
__device__ __forceinline__ float warpRedSum(float v) {
#pragma unroll
    for (int o = 16; o; o >>= 1) v += __shfl_xor_sync(0xffffffffu, v, o);
    return v;
}

// block reduce over 512 threads
__device__ __forceinline__ float blockRed1(float v, float* sred, float* sb,
                                           int lane, int wid) {
    float s = warpRedSum(v);
    if (lane == 0) sred[wid] = s;
    __syncthreads();
    if (wid == 0) {
        float t = (lane < 16) ? sred[lane] : 0.f;
        t = warpRedSum(t);
        if (lane == 0) *sb = t;
    }
    __syncthreads();
    return *sb;
}

// ---------------- K0: coalesced transpose (W1, W2 only) ----------------
__global__ void k_transpose(const float* __restrict__ src, int which, int R, int C) {
    float* dst = (which == 1) ? g_W1t : g_W2t;
    __shared__ float tile[32][33];
    int i = blockIdx.z;
    int c0 = blockIdx.x * 32, r0 = blockIdx.y * 32;
    const float* s = src + (size_t)i * R * C;
    float* dd = dst + (size_t)i * R * C;
    int tx = threadIdx.x, ty = threadIdx.y;
#pragma unroll
    for (int rr = ty; rr < 32; rr += 8)
        tile[rr][tx] = s[(size_t)(r0 + rr) * C + c0 + tx];
    __syncthreads();
#pragma unroll
    for (int cc = ty; cc < 32; cc += 8)
        dd[(size_t)(c0 + cc) * R + r0 + tx] = tile[tx][cc];
}

// ---------------- K1: split-K batched GEMM for proj (no bias/LN here) ----------------
// C_partial[ks][i][b][d] = sum_{k in ks-slab} x[i][b][k] * W[i][d][k]
// block: (ks, ntile, i); 256 threads; m=64(all b), n=64, k=KB, kc=16.
#define KC 16
#define LDS_PAD 68
__global__ __launch_bounds__(256) void k_gemm(const float* __restrict__ x,
                                              const float* __restrict__ W) {
    int ks = blockIdx.x, nt = blockIdx.y, i = blockIdx.z;
    int n0 = nt * 64;
    int tid = threadIdx.x;
    int tx = tid & 15, ty = tid >> 4;          // compute mapping
    int kk = tid & 15, rr = tid >> 4;          // loader mapping

    __shared__ float Xs[KC * LDS_PAD];
    __shared__ float Ws[KC * LDS_PAD];

    const float* xb = x + (size_t)i * NB * ND;
    const float* wb = W + (size_t)i * ND * ND + (size_t)n0 * ND;

    float c[4][4];
#pragma unroll
    for (int q = 0; q < 4; q++)
#pragma unroll
        for (int r = 0; r < 4; r++) c[q][r] = 0.f;

    for (int cc = 0; cc < KB / KC; cc++) {
        int k0 = ks * KB + cc * KC;
#pragma unroll
        for (int r = 0; r < 4; r++) {
            int b = rr + r * 16;
            Xs[kk * LDS_PAD + b] = xb[(size_t)b * ND + k0 + kk];
            Ws[kk * LDS_PAD + b] = wb[(size_t)b * ND + k0 + kk];  // b here = local d
        }
        __syncthreads();
#pragma unroll
        for (int k2 = 0; k2 < KC; k2++) {
            float4 xa = *(const float4*)&Xs[k2 * LDS_PAD + ty * 4];
            float4 wa = *(const float4*)&Ws[k2 * LDS_PAD + tx * 4];
            float xv[4] = {xa.x, xa.y, xa.z, xa.w};
            float wv[4] = {wa.x, wa.y, wa.z, wa.w};
#pragma unroll
            for (int q = 0; q < 4; q++)
#pragma unroll
                for (int r = 0; r < 4; r++) c[q][r] = fmaf(xv[q], wv[r], c[q][r]);
        }
        __syncthreads();
    }
#pragma unroll
    for (int q = 0; q < 4; q++) {
        int b = ty * 4 + q;
        float4 o = make_float4(c[q][0], c[q][1], c[q][2], c[q][3]);
        *(float4*)&g_pp[((size_t)(ks * NM * NB) + i * NB + b) * ND + n0 + tx * 4] = o;
    }
}

// ---------------- K2: per-(i,b) fused: partial-sum + LN + imp1 + imp2 + wf ----------------
__global__ __launch_bounds__(512) void k_post(
        const float* __restrict__ pb, const float* __restrict__ lg,
        const float* __restrict__ lb, const float* __restrict__ b1,
        const float* __restrict__ b2) {
    int i = blockIdx.x >> 6, b = blockIdx.x & 63;
    int tid = threadIdx.x, lane = tid & 31, wid = tid >> 5;
    int d = tid;

    __shared__ float proj_s[ND];
    __shared__ float sP[ND];
    __shared__ float h_s[NDH];
    __shared__ float sred[16];
    __shared__ float sb;

    float acc = 0.f;
#pragma unroll
    for (int s = 0; s < SPLITK; s++)
        acc += g_pp[((size_t)(s * NM * NB) + i * NB + b) * ND + d];
    acc += pb[i * ND + d];

    float mu = blockRed1(acc, sred, &sb, lane, wid) * (1.f / ND);
    float dv = acc - mu;
    float var = blockRed1(dv * dv, sred, &sb, lane, wid) * (1.f / ND);
    float y = dv * rsqrtf(var + 1e-5f) * lg[i * ND + d] + lb[i * ND + d];
    float p = fmaxf(y, 0.f);
    proj_s[d] = p;
    __syncthreads();

    // imp1: k-split by 4
    {
        int dh = tid & 127, k4 = tid >> 7;
        const float* Wt = g_W1t + (size_t)i * ND * NDH + (size_t)(k4 * 128) * NDH + dh;
        float a1 = 0.f;
#pragma unroll 8
        for (int k = 0; k < 128; k++)
            a1 = fmaf(Wt[(size_t)k * NDH], proj_s[k4 * 128 + k], a1);
        sP[k4 * NDH + dh] = a1;
    }
    __syncthreads();
    if (tid < NDH) {
        float hs = sP[tid] + sP[NDH + tid] + sP[2 * NDH + tid] + sP[3 * NDH + tid]
                 + b1[i * NDH + tid];
        h_s[tid] = fmaxf(hs, 0.f);
    }
    __syncthreads();

    // imp2 + sigmoid + wf + rowsum
    const float* W2t = g_W2t + (size_t)i * NDH * ND + d;
    float a2 = 0.f;
#pragma unroll 8
    for (int kh = 0; kh < NDH; kh++)
        a2 = fmaf(W2t[(size_t)kh * ND], h_s[kh], a2);
    a2 += b2[i * ND + d];
    float cw = 1.f / (1.f + __expf(-a2));
    float wfv = proj_s[d] * cw;
    g_wf[((size_t)i * NB + b) * ND + d] = wfv;
    float rs = blockRed1(wfv, sred, &sb, lane, wid);
    if (tid == 0) g_rowsum[i * NB + b] = rs;
}

// ---------------- K3: fused pass1+pass2, packed f32x2, no max-sub, ex2 domain ----------------
__global__ __launch_bounds__(256, 2) void k_pass(const float* __restrict__ modal_bias,
                                                 const float* __restrict__ constraint) {
    int i = blockIdx.x >> 7;
    int db = (blockIdx.x & 127) << 2;
    int tid = threadIdx.x, lane = tid & 31, wid = tid >> 5;
    int dl = wid >> 1, h = wid & 1;
    int d = db + dl;
    int j1 = (i == 0) ? 1 : 0;
    int j2 = (i == 2) ? 1 : 2;
    float c = constraint[i];
    float bias1 = modal_bias[i * NM + j1];
    float bias2 = modal_bias[i * NM + j2];
    float B = 0.8f * c * LOG2E;
    ull C02 = pk2(0.2f, 0.2f);
    ull NB2 = pk2(-B, -B);
    ull PB2 = pk2(B, B);
    ull IHB2 = pk2(INV_HIST_B, INV_HIST_B);

    const float* wfi = g_wf + (size_t)i * NB * ND;
    const float* wf1 = g_wf + (size_t)j1 * NB * ND;
    const float* wf2 = g_wf + (size_t)j2 * NB * ND;
    const float* rs1 = g_rowsum + j1 * NB;
    const float* rs2 = g_rowsum + j2 * NB;

    __shared__ ull sH[8][256];

    // a (pre-scaled into ex2 domain) for this warp's 32 batch rows, one per lane
    float aL_r = wfi[(size_t)(h * 32 + lane) * ND + d] * (INV_SCALE * LOG2E);

    ull H2[8];
#pragma unroll
    for (int kp = 0; kp < 8; kp++) H2[kp] = 0ull;

    // ---- pass A (hist = 0), pair (i, j1) ----
    for (int bb = 0; bb < 32; bb++) {
        int b = h * 32 + bb;
        float a = __shfl_sync(0xffffffffu, aL_r, bb);
        ull a2 = pk2(a, a);
        const ulonglong2* vr = (const ulonglong2*)(wf1 + (size_t)b * ND);
        ull ps2 = 0ull, pd2 = 0ull;
#pragma unroll
        for (int cp = 0; cp < 4; cp++) {
            ulonglong2 qq = vr[lane * 4 + cp];
            ull vv[2] = {qq.x, qq.y};
#pragma unroll
            for (int e = 0; e < 2; e++) {
                int kp = cp * 2 + e;
                ull cur2 = mul2(a2, vv[e]);
                ull u2 = fma2(cur2, C02, NB2);
                ull w2 = fma2(cur2, C02, PB2);
                float x0, x1, u0, u1, w0, w1;
                upk2(cur2, x0, x1); upk2(u2, u0, u1); upk2(w2, w0, w1);
                float f0 = fminf(fmaxf(x0, u0), w0);
                float f1 = fminf(fmaxf(x1, u1), w1);
                H2[kp] = add2(H2[kp], pk2(f0, f1));
                ull pp = pk2(ex2f(f0), ex2f(f1));
                ps2 = add2(ps2, pp);
                pd2 = fma2(pp, vv[e], pd2);
            }
        }
        float s0, s1, d0, d1;
        upk2(ps2, s0, s1); upk2(pd2, d0, d1);
        float ps = warpRedSum(s0 + s1);
        float pd = warpRedSum(d0 + d1);
        if (lane == 0)
            g_att1[((size_t)i * NB + b) * ND + d] = pd / ps + bias1 * rs1[b];
    }

    // exchange history partials between the two half-batch warps of this d
#pragma unroll
    for (int kp = 0; kp < 8; kp++) sH[wid][kp * 32 + lane] = H2[kp];
    __syncthreads();
    ull NH2[8];
    float hsA[16];
#pragma unroll
    for (int kp = 0; kp < 8; kp++) {
        ull hsum = add2(sH[dl * 2][kp * 32 + lane], sH[dl * 2 + 1][kp * 32 + lane]);
        ull hist2 = mul2(hsum, IHB2);
        NH2[kp] = hist2 ^ 0x8000000080000000ULL;
        upk2(hist2, hsA[2 * kp], hsA[2 * kp + 1]);
    }

    // ---- pass B (hist from pass A), pair (i, j2) ----
    for (int bb = 0; bb < 32; bb++) {
        int b = h * 32 + bb;
        float a = __shfl_sync(0xffffffffu, aL_r, bb);
        ull a2 = pk2(a, a);
        const ulonglong2* vr = (const ulonglong2*)(wf2 + (size_t)b * ND);
        ull ps2 = 0ull, pd2 = 0ull;
#pragma unroll
        for (int cp = 0; cp < 4; cp++) {
            ulonglong2 qq = vr[lane * 4 + cp];
            ull vv[2] = {qq.x, qq.y};
#pragma unroll
            for (int e = 0; e < 2; e++) {
                int kp = cp * 2 + e;
                ull x2 = fma2(a2, vv[e], NH2[kp]);   // cur - hist
                ull u2 = fma2(x2, C02, NB2);
                ull w2 = fma2(x2, C02, PB2);
                float x0, x1, u0, u1, w0, w1;
                upk2(x2, x0, x1); upk2(u2, u0, u1); upk2(w2, w0, w1);
                float f0 = fminf(fmaxf(x0, u0), w0) + hsA[2 * kp];
                float f1 = fminf(fmaxf(x1, u1), w1) + hsA[2 * kp + 1];
                ull pp = pk2(ex2f(f0), ex2f(f1));
                ps2 = add2(ps2, pp);
                pd2 = fma2(pp, vv[e], pd2);
            }
        }
        float s0, s1, d0, d1;
        upk2(ps2, s0, s1); upk2(pd2, d0, d1);
        float ps = warpRedSum(s0 + s1);
        float pd = warpRedSum(d0 + d1);
        if (lane == 0)
            g_att2[((size_t)i * NB + b) * ND + d] = pd / ps + bias2 * rs2[b];
    }
}

// ---------------- K4: fuse + attention weights ----------------
__global__ void k_final(const float* __restrict__ gamma, float* __restrict__ out) {
    int b = blockIdx.x, d = threadIdx.x;
    float acc = 0.f;
#pragma unroll
    for (int i = 0; i < NM; i++) {
        int j1 = (i == 0) ? 1 : 0;
        int j2 = (i == 2) ? 1 : 2;
        float g1 = 1.f / (1.f + __expf(-gamma[i * NM + j1]));
        float g2 = 1.f / (1.f + __expf(-gamma[i * NM + j2]));
        int idx = ((i << 6) + b) * ND + d;
        acc += g_wf[idx] + 0.5f * (g1 * g_att1[idx] + g2 * g_att2[idx]);
    }
    out[b * ND + d] = acc * (1.0f / 3.0f);
    if (b == 0 && d == 0) {
        float sc[NM];
        float mx = -3.4e38f;
#pragma unroll
        for (int i = 0; i < NM; i++) {
            int j1 = (i == 0) ? 1 : 0;
            int j2 = (i == 2) ? 1 : 2;
            float g1 = 1.f / (1.f + __expf(-gamma[i * NM + j1]));
            float g2 = 1.f / (1.f + __expf(-gamma[i * NM + j2]));
            sc[i] = 0.5f * (g1 + g2);
            mx = fmaxf(mx, sc[i]);
        }
        float s = 0.f;
#pragma unroll
        for (int i = 0; i < NM; i++) { sc[i] = __expf(sc[i] - mx); s += sc[i]; }
#pragma unroll
        for (int i = 0; i < NM; i++) out[NB * ND + i] = sc[i] / s;
    }
}

extern "C" void kernel_launch(void* const* d_in, const int* in_sizes, int n_in,
                              void* d_out, int out_size) {
    const float* x          = (const float*)d_in[0];
    const float* proj_W     = (const float*)d_in[1];
    const float* proj_b     = (const float*)d_in[2];
    const float* ln_g       = (const float*)d_in[3];
    const float* ln_b       = (const float*)d_in[4];
    const float* imp_W1     = (const float*)d_in[5];
    const float* imp_b1     = (const float*)d_in[6];
    const float* imp_W2     = (const float*)d_in[7];
    const float* imp_b2     = (const float*)d_in[8];
    const float* gamma      = (const float*)d_in[9];
    const float* modal_bias = (const float*)d_in[10];
    const float* constraint = (const float*)d_in[11];
    float* out = (float*)d_out;

    k_transpose<<<dim3(16, 4, NM), dim3(32, 8)>>>(imp_W1, 1, NDH, ND);  // [dh][k]->[k][dh]
    k_transpose<<<dim3(4, 16, NM), dim3(32, 8)>>>(imp_W2, 2, ND, NDH);  // [d][kh]->[kh][d]
    k_gemm<<<dim3(SPLITK, 8, NM), 256>>>(x, proj_W);
    k_post<<<NM * NB, 512>>>(proj_b, ln_g, ln_b, imp_b1, imp_b2);
    k_pass<<<NM * ND / 4, 256>>>(modal_bias, constraint);
    k_final<<<NB, ND>>>(gamma, out);
}

// round 4
// speedup vs baseline: 4.0896x; 1.1132x over previous
#include <cuda_runtime.h>
#include <cuda_bf16.h>

#define NM 3
#define NB 64
#define ND 512
#define NDH 128
#define INV_SCALE 0.04419417382415922f   // 1/sqrt(512)
#define INV_HIST_B 0.003125f             // 1/(64*5)
#define LOG2E 1.4426950408889634f
#define SPLITK 8
#define KB (ND / SPLITK)                 // 64 k per gemm block

typedef unsigned long long ull;

// ---------------- scratch (static device globals; no allocation) ----------------
__device__ __align__(16) float g_pp [SPLITK * NM * NB * ND];  // split-k partials
__device__ __align__(16) float g_W1t[NM * ND * NDH];          // imp_W1^T: [i][k][dh]
__device__ __align__(16) float g_W2t[NM * NDH * ND];          // imp_W2^T: [i][kh][d]
__device__ __align__(16) float g_wf [NM * NB * ND];
__device__ float g_rowsum[NM * NB];
__device__ __align__(16) float g_att1[NM * NB * ND];
__device__ __align__(16) float g_att2[NM * NB * ND];

// ---------------- packed f32x2 helpers ----------------
__device__ __forceinline__ ull pk2(float lo, float hi) {
    ull r; asm("mov.b64 %0, {%1, %2};" : "=l"(r) : "f"(lo), "f"(hi)); return r;
}
__device__ __forceinline__ void upk2(ull v, float& lo, float& hi) {
    asm("mov.b64 {%0, %1}, %2;" : "=f"(lo), "=f"(hi) : "l"(v));
}
__device__ __forceinline__ ull mul2(ull a, ull b) {
    ull r; asm("mul.rn.f32x2 %0, %1, %2;" : "=l"(r) : "l"(a), "l"(b)); return r;
}
__device__ __forceinline__ ull add2(ull a, ull b) {
    ull r; asm("add.rn.f32x2 %0, %1, %2;" : "=l"(r) : "l"(a), "l"(b)); return r;
}
__device__ __forceinline__ ull fma2(ull a, ull b, ull c) {
    ull r; asm("fma.rn.f32x2 %0, %1, %2, %3;" : "=l"(r) : "l"(a), "l"(b), "l"(c)); return r;
}
__device__ __forceinline__ float ex2f(float x) {
    float r; asm("ex2.approx.ftz.f32 %0, %1;" : "=f"(r) : "f"(x)); return r;
}

// ---------------- reduction helpers ----------------
__device__ __forceinline__ float warpRedSum(float v) {
#pragma unroll
    for (int o = 16; o; o >>= 1) v += __shfl_xor_sync(0xffffffffu, v, o);
    return v;
}

// block reduce over 256 threads (8 warps)
__device__ __forceinline__ float blockRed256(float v, float* sred, float* sb,
                                             int lane, int wid) {
    float s = warpRedSum(v);
    if (lane == 0) sred[wid] = s;
    __syncthreads();
    if (wid == 0) {
        float t = (lane < 8) ? sred[lane] : 0.f;
        t = warpRedSum(t);
        if (lane == 0) *sb = t;
    }
    __syncthreads();
    return *sb;
}

// ---------------- K0: merged coalesced transposes (W1 and W2) ----------------
// z < NM: W1 mode z (R=128,C=512); z >= NM: W2 mode z-NM (R=512,C=128).
__global__ void k_trans(const float* __restrict__ W1, const float* __restrict__ W2) {
    __shared__ float tile[32][33];
    int z = blockIdx.z;
    int t = blockIdx.x;
    int isW2 = (z >= NM);
    int i = isW2 ? z - NM : z;
    int R = isW2 ? ND : NDH;
    int C = isW2 ? NDH : ND;
    int c0 = (isW2 ? (t & 3) : (t & 15)) * 32;
    int r0 = (isW2 ? (t >> 2) : (t >> 4)) * 32;
    const float* s = (isW2 ? W2 : W1) + (size_t)i * R * C;
    float* dd = (isW2 ? g_W2t : g_W1t) + (size_t)i * R * C;
    int tx = threadIdx.x, ty = threadIdx.y;
#pragma unroll
    for (int rr = ty; rr < 32; rr += 8)
        tile[rr][tx] = s[(size_t)(r0 + rr) * C + c0 + tx];
    __syncthreads();
#pragma unroll
    for (int cc = ty; cc < 32; cc += 8)
        dd[(size_t)(c0 + cc) * R + r0 + tx] = tile[tx][cc];
}

// ---------------- K1: split-K batched GEMM for proj ----------------
#define KC 16
#define LDS_PAD 68
__global__ __launch_bounds__(256) void k_gemm(const float* __restrict__ x,
                                              const float* __restrict__ W) {
    int ks = blockIdx.x, nt = blockIdx.y, i = blockIdx.z;
    int n0 = nt * 64;
    int tid = threadIdx.x;
    int tx = tid & 15, ty = tid >> 4;
    int kk = tid & 15, rr = tid >> 4;

    __shared__ float Xs[KC * LDS_PAD];
    __shared__ float Ws[KC * LDS_PAD];

    const float* xb = x + (size_t)i * NB * ND;
    const float* wb = W + (size_t)i * ND * ND + (size_t)n0 * ND;

    float c[4][4];
#pragma unroll
    for (int q = 0; q < 4; q++)
#pragma unroll
        for (int r = 0; r < 4; r++) c[q][r] = 0.f;

    for (int cc = 0; cc < KB / KC; cc++) {
        int k0 = ks * KB + cc * KC;
#pragma unroll
        for (int r = 0; r < 4; r++) {
            int b = rr + r * 16;
            Xs[kk * LDS_PAD + b] = xb[(size_t)b * ND + k0 + kk];
            Ws[kk * LDS_PAD + b] = wb[(size_t)b * ND + k0 + kk];
        }
        __syncthreads();
#pragma unroll
        for (int k2 = 0; k2 < KC; k2++) {
            float4 xa = *(const float4*)&Xs[k2 * LDS_PAD + ty * 4];
            float4 wa = *(const float4*)&Ws[k2 * LDS_PAD + tx * 4];
            float xv[4] = {xa.x, xa.y, xa.z, xa.w};
            float wv[4] = {wa.x, wa.y, wa.z, wa.w};
#pragma unroll
            for (int q = 0; q < 4; q++)
#pragma unroll
                for (int r = 0; r < 4; r++) c[q][r] = fmaf(xv[q], wv[r], c[q][r]);
        }
        __syncthreads();
    }
#pragma unroll
    for (int q = 0; q < 4; q++) {
        int b = ty * 4 + q;
        float4 o = make_float4(c[q][0], c[q][1], c[q][2], c[q][3]);
        *(float4*)&g_pp[((size_t)(ks * NM * NB) + i * NB + b) * ND + n0 + tx * 4] = o;
    }
}

// ---------------- K2: per-(i,b) fused epilogue: 256 threads, 2 d per thread ----------------
__global__ __launch_bounds__(256) void k_post(
        const float* __restrict__ pb, const float* __restrict__ lg,
        const float* __restrict__ lb, const float* __restrict__ b1,
        const float* __restrict__ b2) {
    int i = blockIdx.x >> 6, b = blockIdx.x & 63;
    int tid = threadIdx.x, lane = tid & 31, wid = tid >> 5;
    int d0 = tid, d1 = tid + 256;

    __shared__ float proj_s[ND];
    __shared__ float sP[2 * NDH];
    __shared__ float h_s[NDH];
    __shared__ float sred[8];
    __shared__ float sb;

    // split-k partial sum (16 independent loads)
    float acc0 = 0.f, acc1 = 0.f;
#pragma unroll
    for (int s = 0; s < SPLITK; s++) {
        const float* pp = g_pp + ((size_t)(s * NM * NB) + i * NB + b) * ND;
        acc0 += pp[d0];
        acc1 += pp[d1];
    }
    acc0 += pb[i * ND + d0];
    acc1 += pb[i * ND + d1];

    // LayerNorm over 512 d (2 per thread)
    float mu = blockRed256(acc0 + acc1, sred, &sb, lane, wid) * (1.f / ND);
    float dv0 = acc0 - mu, dv1 = acc1 - mu;
    float var = blockRed256(dv0 * dv0 + dv1 * dv1, sred, &sb, lane, wid) * (1.f / ND);
    float rstd = rsqrtf(var + 1e-5f);
    float p0 = fmaxf(dv0 * rstd * lg[i * ND + d0] + lb[i * ND + d0], 0.f);
    float p1 = fmaxf(dv1 * rstd * lg[i * ND + d1] + lb[i * ND + d1], 0.f);
    proj_s[d0] = p0;
    proj_s[d1] = p1;
    __syncthreads();

    // imp1: 128 dh x 2 k-splits of 256, 4 accumulators each
    {
        int dh = tid & 127, k4 = tid >> 7;
        const float* Wt = g_W1t + (size_t)i * ND * NDH + (size_t)(k4 * 256) * NDH + dh;
        const float* ps = proj_s + k4 * 256;
        float a[4] = {0.f, 0.f, 0.f, 0.f};
#pragma unroll 8
        for (int k = 0; k < 256; k += 4) {
            a[0] = fmaf(Wt[(size_t)(k + 0) * NDH], ps[k + 0], a[0]);
            a[1] = fmaf(Wt[(size_t)(k + 1) * NDH], ps[k + 1], a[1]);
            a[2] = fmaf(Wt[(size_t)(k + 2) * NDH], ps[k + 2], a[2]);
            a[3] = fmaf(Wt[(size_t)(k + 3) * NDH], ps[k + 3], a[3]);
        }
        sP[k4 * NDH + dh] = (a[0] + a[1]) + (a[2] + a[3]);
    }
    __syncthreads();
    if (tid < NDH) {
        float hs = sP[tid] + sP[NDH + tid] + b1[i * NDH + tid];
        h_s[tid] = fmaxf(hs, 0.f);
    }
    __syncthreads();

    // imp2: both d's, 4 accumulators each (8 loads / 4 kh)
    {
        const float* W2t = g_W2t + (size_t)i * NDH * ND;
        float c0[4] = {0.f, 0.f, 0.f, 0.f};
        float c1[4] = {0.f, 0.f, 0.f, 0.f};
#pragma unroll 4
        for (int kh = 0; kh < NDH; kh += 4) {
#pragma unroll
            for (int j = 0; j < 4; j++) {
                float h = h_s[kh + j];
                c0[j] = fmaf(W2t[(size_t)(kh + j) * ND + d0], h, c0[j]);
                c1[j] = fmaf(W2t[(size_t)(kh + j) * ND + d1], h, c1[j]);
            }
        }
        float a20 = (c0[0] + c0[1]) + (c0[2] + c0[3]) + b2[i * ND + d0];
        float a21 = (c1[0] + c1[1]) + (c1[2] + c1[3]) + b2[i * ND + d1];
        float cw0 = 1.f / (1.f + __expf(-a20));
        float cw1 = 1.f / (1.f + __expf(-a21));
        float wf0 = p0 * cw0, wf1 = p1 * cw1;
        float* wfo = g_wf + ((size_t)i * NB + b) * ND;
        wfo[d0] = wf0;
        wfo[d1] = wf1;
        float rs = blockRed256(wf0 + wf1, sred, &sb, lane, wid);
        if (tid == 0) g_rowsum[i * NB + b] = rs;
    }
}

// ---------------- K3: fused pass1+pass2, packed f32x2, ex2 domain ----------------
__global__ __launch_bounds__(256, 3) void k_pass(const float* __restrict__ modal_bias,
                                                 const float* __restrict__ constraint) {
    int i = blockIdx.x >> 7;
    int db = (blockIdx.x & 127) << 2;
    int tid = threadIdx.x, lane = tid & 31, wid = tid >> 5;
    int dl = wid >> 1, h = wid & 1;
    int d = db + dl;
    int j1 = (i == 0) ? 1 : 0;
    int j2 = (i == 2) ? 1 : 2;
    float c = constraint[i];
    float bias1 = modal_bias[i * NM + j1];
    float bias2 = modal_bias[i * NM + j2];
    float B = 0.8f * c * LOG2E;
    ull C02 = pk2(0.2f, 0.2f);
    ull NB2 = pk2(-B, -B);
    ull PB2 = pk2(B, B);
    ull IHB2 = pk2(INV_HIST_B, INV_HIST_B);

    const float* wfi = g_wf + (size_t)i * NB * ND;
    const float* wf1 = g_wf + (size_t)j1 * NB * ND;
    const float* wf2 = g_wf + (size_t)j2 * NB * ND;
    const float* rs1 = g_rowsum + j1 * NB;
    const float* rs2 = g_rowsum + j2 * NB;

    __shared__ ull sH[8][256];

    // a (pre-scaled into ex2 domain) for this warp's 32 batch rows, one per lane
    float aL_r = wfi[(size_t)(h * 32 + lane) * ND + d] * (INV_SCALE * LOG2E);

    ull H2[8];
#pragma unroll
    for (int kp = 0; kp < 8; kp++) H2[kp] = 0ull;

    // ---- pass A (hist = 0), pair (i, j1) ----
    for (int bb = 0; bb < 32; bb++) {
        int b = h * 32 + bb;
        float a = __shfl_sync(0xffffffffu, aL_r, bb);
        ull a2 = pk2(a, a);
        const ulonglong2* vr = (const ulonglong2*)(wf1 + (size_t)b * ND);
        ull ps2 = 0ull, pd2 = 0ull;
#pragma unroll
        for (int cp = 0; cp < 4; cp++) {
            ulonglong2 qq = vr[lane * 4 + cp];
            ull vv[2] = {qq.x, qq.y};
#pragma unroll
            for (int e = 0; e < 2; e++) {
                int kp = cp * 2 + e;
                ull cur2 = mul2(a2, vv[e]);
                ull u2 = fma2(cur2, C02, NB2);
                ull w2 = fma2(cur2, C02, PB2);
                float x0, x1, u0, u1, w0, w1;
                upk2(cur2, x0, x1); upk2(u2, u0, u1); upk2(w2, w0, w1);
                float f0 = fminf(fmaxf(x0, u0), w0);
                float f1 = fminf(fmaxf(x1, u1), w1);
                H2[kp] = add2(H2[kp], pk2(f0, f1));
                ull pp = pk2(ex2f(f0), ex2f(f1));
                ps2 = add2(ps2, pp);
                pd2 = fma2(pp, vv[e], pd2);
            }
        }
        float s0, s1, dd0, dd1;
        upk2(ps2, s0, s1); upk2(pd2, dd0, dd1);
        float ps = warpRedSum(s0 + s1);
        float pd = warpRedSum(dd0 + dd1);
        if (lane == 0)
            g_att1[((size_t)i * NB + b) * ND + d] = pd / ps + bias1 * rs1[b];
    }

    // exchange history partials between the two half-batch warps of this d
#pragma unroll
    for (int kp = 0; kp < 8; kp++) sH[wid][kp * 32 + lane] = H2[kp];
    __syncthreads();
    ull NH2[8];   // packed NEGATED history
#pragma unroll
    for (int kp = 0; kp < 8; kp++) {
        ull hsum = add2(sH[dl * 2][kp * 32 + lane], sH[dl * 2 + 1][kp * 32 + lane]);
        NH2[kp] = mul2(hsum, IHB2) ^ 0x8000000080000000ULL;
    }

    // ---- pass B (hist from pass A), pair (i, j2) ----
    for (int bb = 0; bb < 32; bb++) {
        int b = h * 32 + bb;
        float a = __shfl_sync(0xffffffffu, aL_r, bb);
        ull a2 = pk2(a, a);
        const ulonglong2* vr = (const ulonglong2*)(wf2 + (size_t)b * ND);
        ull ps2 = 0ull, pd2 = 0ull;
#pragma unroll
        for (int cp = 0; cp < 4; cp++) {
            ulonglong2 qq = vr[lane * 4 + cp];
            ull vv[2] = {qq.x, qq.y};
#pragma unroll
            for (int e = 0; e < 2; e++) {
                int kp = cp * 2 + e;
                ull x2 = fma2(a2, vv[e], NH2[kp]);   // cur - hist
                ull u2 = fma2(x2, C02, NB2);
                ull w2 = fma2(x2, C02, PB2);
                float x0, x1, u0, u1, w0, w1, nh0, nh1;
                upk2(x2, x0, x1); upk2(u2, u0, u1); upk2(w2, w0, w1);
                upk2(NH2[kp], nh0, nh1);
                float f0 = fminf(fmaxf(x0, u0), w0) - nh0;
                float f1 = fminf(fmaxf(x1, u1), w1) - nh1;
                ull pp = pk2(ex2f(f0), ex2f(f1));
                ps2 = add2(ps2, pp);
                pd2 = fma2(pp, vv[e], pd2);
            }
        }
        float s0, s1, dd0, dd1;
        upk2(ps2, s0, s1); upk2(pd2, dd0, dd1);
        float ps = warpRedSum(s0 + s1);
        float pd = warpRedSum(dd0 + dd1);
        if (lane == 0)
            g_att2[((size_t)i * NB + b) * ND + d] = pd / ps + bias2 * rs2[b];
    }
}

// ---------------- K4: fuse + attention weights ----------------
__global__ void k_final(const float* __restrict__ gamma, float* __restrict__ out) {
    int b = blockIdx.x, d = threadIdx.x;
    float acc = 0.f;
#pragma unroll
    for (int i = 0; i < NM; i++) {
        int j1 = (i == 0) ? 1 : 0;
        int j2 = (i == 2) ? 1 : 2;
        float g1 = 1.f / (1.f + __expf(-gamma[i * NM + j1]));
        float g2 = 1.f / (1.f + __expf(-gamma[i * NM + j2]));
        int idx = ((i << 6) + b) * ND + d;
        acc += g_wf[idx] + 0.5f * (g1 * g_att1[idx] + g2 * g_att2[idx]);
    }
    out[b * ND + d] = acc * (1.0f / 3.0f);
    if (b == 0 && d == 0) {
        float sc[NM];
        float mx = -3.4e38f;
#pragma unroll
        for (int i = 0; i < NM; i++) {
            int j1 = (i == 0) ? 1 : 0;
            int j2 = (i == 2) ? 1 : 2;
            float g1 = 1.f / (1.f + __expf(-gamma[i * NM + j1]));
            float g2 = 1.f / (1.f + __expf(-gamma[i * NM + j2]));
            sc[i] = 0.5f * (g1 + g2);
            mx = fmaxf(mx, sc[i]);
        }
        float s = 0.f;
#pragma unroll
        for (int i = 0; i < NM; i++) { sc[i] = __expf(sc[i] - mx); s += sc[i]; }
#pragma unroll
        for (int i = 0; i < NM; i++) out[NB * ND + i] = sc[i] / s;
    }
}

extern "C" void kernel_launch(void* const* d_in, const int* in_sizes, int n_in,
                              void* d_out, int out_size) {
    const float* x          = (const float*)d_in[0];
    const float* proj_W     = (const float*)d_in[1];
    const float* proj_b     = (const float*)d_in[2];
    const float* ln_g       = (const float*)d_in[3];
    const float* ln_b       = (const float*)d_in[4];
    const float* imp_W1     = (const float*)d_in[5];
    const float* imp_b1     = (const float*)d_in[6];
    const float* imp_W2     = (const float*)d_in[7];
    const float* imp_b2     = (const float*)d_in[8];
    const float* gamma      = (const float*)d_in[9];
    const float* modal_bias = (const float*)d_in[10];
    const float* constraint = (const float*)d_in[11];
    float* out = (float*)d_out;

    k_trans<<<dim3(64, 1, 2 * NM), dim3(32, 8)>>>(imp_W1, imp_W2);
    k_gemm<<<dim3(SPLITK, 8, NM), 256>>>(x, proj_W);
    k_post<<<NM * NB, 256>>>(proj_b, ln_g, ln_b, imp_b1, imp_b2);
    k_pass<<<NM * ND / 4, 256>>>(modal_bias, constraint);
    k_final<<<NB, ND>>>(gamma, out);
}

// round 6
// speedup vs baseline: 4.7372x; 1.1584x over previous
#include <cuda_runtime.h>
#include <cuda_bf16.h>

// v5b — identical to v5; resubmitted after harness-side "system not yet
// initialized" (device init failed before any kernel ran; infra transient).

#define NM 3
#define NB 64
#define ND 512
#define NDH 128
#define INV_SCALE 0.04419417382415922f   // 1/sqrt(512)
#define INV_HIST_B 0.003125f             // 1/(64*5)
#define LOG2E 1.4426950408889634f
#define SPLITK 16
#define KB (ND / SPLITK)                 // 32 k per gemm block

typedef unsigned long long ull;

// ---------------- scratch (static device globals; no allocation) ----------------
__device__ __align__(16) float g_pp [SPLITK * NM * NB * ND];  // split-k partials
__device__ __align__(16) float g_W1t[NM * ND * NDH];          // imp_W1^T: [i][k][dh]
__device__ __align__(16) float g_W2t[NM * NDH * ND];          // imp_W2^T: [i][kh][d]
__device__ __align__(16) float g_wf [NM * NB * ND];
__device__ float g_rowsum[NM * NB];
__device__ __align__(16) float g_att1[NM * NB * ND];
__device__ __align__(16) float g_att2[NM * NB * ND];

// ---------------- packed f32x2 helpers ----------------
__device__ __forceinline__ ull pk2(float lo, float hi) {
    ull r; asm("mov.b64 %0, {%1, %2};" : "=l"(r) : "f"(lo), "f"(hi)); return r;
}
__device__ __forceinline__ void upk2(ull v, float& lo, float& hi) {
    asm("mov.b64 {%0, %1}, %2;" : "=f"(lo), "=f"(hi) : "l"(v));
}
__device__ __forceinline__ ull mul2(ull a, ull b) {
    ull r; asm("mul.rn.f32x2 %0, %1, %2;" : "=l"(r) : "l"(a), "l"(b)); return r;
}
__device__ __forceinline__ ull add2(ull a, ull b) {
    ull r; asm("add.rn.f32x2 %0, %1, %2;" : "=l"(r) : "l"(a), "l"(b)); return r;
}
__device__ __forceinline__ ull fma2(ull a, ull b, ull c) {
    ull r; asm("fma.rn.f32x2 %0, %1, %2, %3;" : "=l"(r) : "l"(a), "l"(b), "l"(c)); return r;
}
__device__ __forceinline__ float ex2f(float x) {
    float r; asm("ex2.approx.ftz.f32 %0, %1;" : "=f"(r) : "f"(x)); return r;
}

// ---------------- reduction helpers ----------------
__device__ __forceinline__ float warpRedSum(float v) {
#pragma unroll
    for (int o = 16; o; o >>= 1) v += __shfl_xor_sync(0xffffffffu, v, o);
    return v;
}

// block reduce over 256 threads (8 warps)
__device__ __forceinline__ float blockRed256(float v, float* sred, float* sb,
                                             int lane, int wid) {
    float s = warpRedSum(v);
    if (lane == 0) sred[wid] = s;
    __syncthreads();
    if (wid == 0) {
        float t = (lane < 8) ? sred[lane] : 0.f;
        t = warpRedSum(t);
        if (lane == 0) *sb = t;
    }
    __syncthreads();
    return *sb;
}

// ---------------- K1: merged prep: split-K proj GEMM + W1/W2 transposes ----------------
// blocks [0, 384): gemm (ks = b&15, nt = (b>>4)&7, i = b>>7)
// blocks [384, 768): transpose (t = (b-384)&63, z = (b-384)>>6)
#define KC 16
#define LDS_PAD 68
#define GEMM_BLOCKS (SPLITK * 8 * NM)
__global__ __launch_bounds__(256) void k_prep(const float* __restrict__ x,
                                              const float* __restrict__ W,
                                              const float* __restrict__ W1,
                                              const float* __restrict__ W2) {
    int bid = blockIdx.x;
    int tid = threadIdx.x;
    if (bid < GEMM_BLOCKS) {
        int ks = bid & 15, nt = (bid >> 4) & 7, i = bid >> 7;
        int n0 = nt * 64;
        int tx = tid & 15, ty = tid >> 4;
        int kk = tid & 15, rr = tid >> 4;

        __shared__ float Xs[KC * LDS_PAD];
        __shared__ float Ws[KC * LDS_PAD];

        const float* xb = x + (size_t)i * NB * ND;
        const float* wb = W + (size_t)i * ND * ND + (size_t)n0 * ND;

        float c[4][4];
#pragma unroll
        for (int q = 0; q < 4; q++)
#pragma unroll
            for (int r = 0; r < 4; r++) c[q][r] = 0.f;

#pragma unroll
        for (int cc = 0; cc < KB / KC; cc++) {
            int k0 = ks * KB + cc * KC;
#pragma unroll
            for (int r = 0; r < 4; r++) {
                int b = rr + r * 16;
                Xs[kk * LDS_PAD + b] = xb[(size_t)b * ND + k0 + kk];
                Ws[kk * LDS_PAD + b] = wb[(size_t)b * ND + k0 + kk];
            }
            __syncthreads();
#pragma unroll
            for (int k2 = 0; k2 < KC; k2++) {
                float4 xa = *(const float4*)&Xs[k2 * LDS_PAD + ty * 4];
                float4 wa = *(const float4*)&Ws[k2 * LDS_PAD + tx * 4];
                float xv[4] = {xa.x, xa.y, xa.z, xa.w};
                float wv[4] = {wa.x, wa.y, wa.z, wa.w};
#pragma unroll
                for (int q = 0; q < 4; q++)
#pragma unroll
                    for (int r = 0; r < 4; r++) c[q][r] = fmaf(xv[q], wv[r], c[q][r]);
            }
            __syncthreads();
        }
#pragma unroll
        for (int q = 0; q < 4; q++) {
            int b = ty * 4 + q;
            float4 o = make_float4(c[q][0], c[q][1], c[q][2], c[q][3]);
            *(float4*)&g_pp[((size_t)(ks * NM * NB) + i * NB + b) * ND + n0 + tx * 4] = o;
        }
    } else {
        // transpose: z < NM -> W1 mode z (R=128,C=512); else W2 mode z-NM (R=512,C=128)
        __shared__ float tile[32][33];
        int t = (bid - GEMM_BLOCKS) & 63;
        int z = (bid - GEMM_BLOCKS) >> 6;
        int isW2 = (z >= NM);
        int i = isW2 ? z - NM : z;
        int R = isW2 ? ND : NDH;
        int C = isW2 ? NDH : ND;
        int c0 = (isW2 ? (t & 3) : (t & 15)) * 32;
        int r0 = (isW2 ? (t >> 2) : (t >> 4)) * 32;
        const float* s = (isW2 ? W2 : W1) + (size_t)i * R * C;
        float* dd = (isW2 ? g_W2t : g_W1t) + (size_t)i * R * C;
        int tx = tid & 31, ty = tid >> 5;
#pragma unroll
        for (int rr = ty; rr < 32; rr += 8)
            tile[rr][tx] = s[(size_t)(r0 + rr) * C + c0 + tx];
        __syncthreads();
#pragma unroll
        for (int cc = ty; cc < 32; cc += 8)
            dd[(size_t)(c0 + cc) * R + r0 + tx] = tile[tx][cc];
    }
}

// ---------------- K2: per-(i,b) fused epilogue: 256 threads, 2 d per thread ----------------
__global__ __launch_bounds__(256) void k_post(
        const float* __restrict__ pb, const float* __restrict__ lg,
        const float* __restrict__ lb, const float* __restrict__ b1,
        const float* __restrict__ b2) {
    int i = blockIdx.x >> 6, b = blockIdx.x & 63;
    int tid = threadIdx.x, lane = tid & 31, wid = tid >> 5;
    int d0 = tid, d1 = tid + 256;

    __shared__ float proj_s[ND];
    __shared__ float sP[2 * NDH];
    __shared__ float h_s[NDH];
    __shared__ float sred[8];
    __shared__ float sb;

    // split-k partial sum (32 independent loads)
    float acc0 = 0.f, acc1 = 0.f;
#pragma unroll
    for (int s = 0; s < SPLITK; s++) {
        const float* pp = g_pp + ((size_t)(s * NM * NB) + i * NB + b) * ND;
        acc0 += pp[d0];
        acc1 += pp[d1];
    }
    acc0 += pb[i * ND + d0];
    acc1 += pb[i * ND + d1];

    // LayerNorm over 512 d (2 per thread)
    float mu = blockRed256(acc0 + acc1, sred, &sb, lane, wid) * (1.f / ND);
    float dv0 = acc0 - mu, dv1 = acc1 - mu;
    float var = blockRed256(dv0 * dv0 + dv1 * dv1, sred, &sb, lane, wid) * (1.f / ND);
    float rstd = rsqrtf(var + 1e-5f);
    float p0 = fmaxf(dv0 * rstd * lg[i * ND + d0] + lb[i * ND + d0], 0.f);
    float p1 = fmaxf(dv1 * rstd * lg[i * ND + d1] + lb[i * ND + d1], 0.f);
    proj_s[d0] = p0;
    proj_s[d1] = p1;
    __syncthreads();

    // imp1: 128 dh x 2 k-splits of 256, 4 accumulators each
    {
        int dh = tid & 127, k4 = tid >> 7;
        const float* Wt = g_W1t + (size_t)i * ND * NDH + (size_t)(k4 * 256) * NDH + dh;
        const float* ps = proj_s + k4 * 256;
        float a[4] = {0.f, 0.f, 0.f, 0.f};
#pragma unroll 8
        for (int k = 0; k < 256; k += 4) {
            a[0] = fmaf(Wt[(size_t)(k + 0) * NDH], ps[k + 0], a[0]);
            a[1] = fmaf(Wt[(size_t)(k + 1) * NDH], ps[k + 1], a[1]);
            a[2] = fmaf(Wt[(size_t)(k + 2) * NDH], ps[k + 2], a[2]);
            a[3] = fmaf(Wt[(size_t)(k + 3) * NDH], ps[k + 3], a[3]);
        }
        sP[k4 * NDH + dh] = (a[0] + a[1]) + (a[2] + a[3]);
    }
    __syncthreads();
    if (tid < NDH) {
        float hs = sP[tid] + sP[NDH + tid] + b1[i * NDH + tid];
        h_s[tid] = fmaxf(hs, 0.f);
    }
    __syncthreads();

    // imp2: both d's, 4 accumulators each
    {
        const float* W2t = g_W2t + (size_t)i * NDH * ND;
        float c0[4] = {0.f, 0.f, 0.f, 0.f};
        float c1[4] = {0.f, 0.f, 0.f, 0.f};
#pragma unroll 4
        for (int kh = 0; kh < NDH; kh += 4) {
#pragma unroll
            for (int j = 0; j < 4; j++) {
                float h = h_s[kh + j];
                c0[j] = fmaf(W2t[(size_t)(kh + j) * ND + d0], h, c0[j]);
                c1[j] = fmaf(W2t[(size_t)(kh + j) * ND + d1], h, c1[j]);
            }
        }
        float a20 = (c0[0] + c0[1]) + (c0[2] + c0[3]) + b2[i * ND + d0];
        float a21 = (c1[0] + c1[1]) + (c1[2] + c1[3]) + b2[i * ND + d1];
        float cw0 = 1.f / (1.f + __expf(-a20));
        float cw1 = 1.f / (1.f + __expf(-a21));
        float wf0 = p0 * cw0, wf1 = p1 * cw1;
        float* wfo = g_wf + ((size_t)i * NB + b) * ND;
        wfo[d0] = wf0;
        wfo[d1] = wf1;
        float rs = blockRed256(wf0 + wf1, sred, &sb, lane, wid);
        if (tid == 0) g_rowsum[i * NB + b] = rs;
    }
}

// ---------------- K3: fused pass1+pass2, coalesced v loads, packed f32x2 ----------------
__global__ __launch_bounds__(256, 3) void k_pass(const float* __restrict__ modal_bias,
                                                 const float* __restrict__ constraint) {
    int i = blockIdx.x >> 7;
    int db = (blockIdx.x & 127) << 2;
    int tid = threadIdx.x, lane = tid & 31, wid = tid >> 5;
    int dl = wid >> 1, h = wid & 1;
    int d = db + dl;
    int j1 = (i == 0) ? 1 : 0;
    int j2 = (i == 2) ? 1 : 2;
    float c = constraint[i];
    float bias1 = modal_bias[i * NM + j1];
    float bias2 = modal_bias[i * NM + j2];
    float B = 0.8f * c * LOG2E;
    ull C02 = pk2(0.2f, 0.2f);
    ull NB2 = pk2(-B, -B);
    ull PB2 = pk2(B, B);
    ull IHB2 = pk2(INV_HIST_B, INV_HIST_B);

    const float* wfi = g_wf + (size_t)i * NB * ND;
    const float* wf1 = g_wf + (size_t)j1 * NB * ND;
    const float* wf2 = g_wf + (size_t)j2 * NB * ND;
    const float* rs1 = g_rowsum + j1 * NB;
    const float* rs2 = g_rowsum + j2 * NB;

    __shared__ ull sH[8][256];

    // a (pre-scaled into ex2 domain) for this warp's 32 batch rows, one per lane
    float aL_r = wfi[(size_t)(h * 32 + lane) * ND + d] * (INV_SCALE * LOG2E);

    ull H2[8];
#pragma unroll
    for (int kp = 0; kp < 8; kp++) H2[kp] = 0ull;

    // ---- pass A (hist = 0), pair (i, j1) ----
    for (int bb = 0; bb < 32; bb++) {
        int b = h * 32 + bb;
        float a = __shfl_sync(0xffffffffu, aL_r, bb);
        ull a2 = pk2(a, a);
        const ulonglong2* vr = (const ulonglong2*)(wf1 + (size_t)b * ND);
        // coalesced: lane-contiguous 16B chunks
        ulonglong2 q0 = vr[lane], q1 = vr[32 + lane], q2 = vr[64 + lane], q3 = vr[96 + lane];
        ull vv[8] = {q0.x, q0.y, q1.x, q1.y, q2.x, q2.y, q3.x, q3.y};
        ull ps2 = 0ull, pd2 = 0ull;
#pragma unroll
        for (int kp = 0; kp < 8; kp++) {
            ull cur2 = mul2(a2, vv[kp]);
            ull u2 = fma2(cur2, C02, NB2);
            ull w2 = fma2(cur2, C02, PB2);
            float x0, x1, u0, u1, w0, w1;
            upk2(cur2, x0, x1); upk2(u2, u0, u1); upk2(w2, w0, w1);
            float f0 = fminf(fmaxf(x0, u0), w0);
            float f1 = fminf(fmaxf(x1, u1), w1);
            H2[kp] = add2(H2[kp], pk2(f0, f1));
            ull pp = pk2(ex2f(f0), ex2f(f1));
            ps2 = add2(ps2, pp);
            pd2 = fma2(pp, vv[kp], pd2);
        }
        float s0, s1, dd0, dd1;
        upk2(ps2, s0, s1); upk2(pd2, dd0, dd1);
        float ps = warpRedSum(s0 + s1);
        float pd = warpRedSum(dd0 + dd1);
        if (lane == 0)
            g_att1[((size_t)i * NB + b) * ND + d] = pd / ps + bias1 * rs1[b];
    }

    // exchange history partials between the two half-batch warps of this d
#pragma unroll
    for (int kp = 0; kp < 8; kp++) sH[wid][kp * 32 + lane] = H2[kp];
    __syncthreads();
    ull NH2[8];   // packed NEGATED history
#pragma unroll
    for (int kp = 0; kp < 8; kp++) {
        ull hsum = add2(sH[dl * 2][kp * 32 + lane], sH[dl * 2 + 1][kp * 32 + lane]);
        NH2[kp] = mul2(hsum, IHB2) ^ 0x8000000080000000ULL;
    }

    // ---- pass B (hist from pass A), pair (i, j2) ----
    for (int bb = 0; bb < 32; bb++) {
        int b = h * 32 + bb;
        float a = __shfl_sync(0xffffffffu, aL_r, bb);
        ull a2 = pk2(a, a);
        const ulonglong2* vr = (const ulonglong2*)(wf2 + (size_t)b * ND);
        ulonglong2 q0 = vr[lane], q1 = vr[32 + lane], q2 = vr[64 + lane], q3 = vr[96 + lane];
        ull vv[8] = {q0.x, q0.y, q1.x, q1.y, q2.x, q2.y, q3.x, q3.y};
        ull ps2 = 0ull, pd2 = 0ull;
#pragma unroll
        for (int kp = 0; kp < 8; kp++) {
            ull x2 = fma2(a2, vv[kp], NH2[kp]);   // cur - hist
            ull u2 = fma2(x2, C02, NB2);
            ull w2 = fma2(x2, C02, PB2);
            float x0, x1, u0, u1, w0, w1, nh0, nh1;
            upk2(x2, x0, x1); upk2(u2, u0, u1); upk2(w2, w0, w1);
            upk2(NH2[kp], nh0, nh1);
            float f0 = fminf(fmaxf(x0, u0), w0) - nh0;
            float f1 = fminf(fmaxf(x1, u1), w1) - nh1;
            ull pp = pk2(ex2f(f0), ex2f(f1));
            ps2 = add2(ps2, pp);
            pd2 = fma2(pp, vv[kp], pd2);
        }
        float s0, s1, dd0, dd1;
        upk2(ps2, s0, s1); upk2(pd2, dd0, dd1);
        float ps = warpRedSum(s0 + s1);
        float pd = warpRedSum(dd0 + dd1);
        if (lane == 0)
            g_att2[((size_t)i * NB + b) * ND + d] = pd / ps + bias2 * rs2[b];
    }
}

// ---------------- K4: fuse + attention weights ----------------
__global__ void k_final(const float* __restrict__ gamma, float* __restrict__ out) {
    int b = blockIdx.x, d = threadIdx.x;
    float acc = 0.f;
#pragma unroll
    for (int i = 0; i < NM; i++) {
        int j1 = (i == 0) ? 1 : 0;
        int j2 = (i == 2) ? 1 : 2;
        float g1 = 1.f / (1.f + __expf(-gamma[i * NM + j1]));
        float g2 = 1.f / (1.f + __expf(-gamma[i * NM + j2]));
        int idx = ((i << 6) + b) * ND + d;
        acc += g_wf[idx] + 0.5f * (g1 * g_att1[idx] + g2 * g_att2[idx]);
    }
    out[b * ND + d] = acc * (1.0f / 3.0f);
    if (b == 0 && d == 0) {
        float sc[NM];
        float mx = -3.4e38f;
#pragma unroll
        for (int i = 0; i < NM; i++) {
            int j1 = (i == 0) ? 1 : 0;
            int j2 = (i == 2) ? 1 : 2;
            float g1 = 1.f / (1.f + __expf(-gamma[i * NM + j1]));
            float g2 = 1.f / (1.f + __expf(-gamma[i * NM + j2]));
            sc[i] = 0.5f * (g1 + g2);
            mx = fmaxf(mx, sc[i]);
        }
        float s = 0.f;
#pragma unroll
        for (int i = 0; i < NM; i++) { sc[i] = __expf(sc[i] - mx); s += sc[i]; }
#pragma unroll
        for (int i = 0; i < NM; i++) out[NB * ND + i] = sc[i] / s;
    }
}

extern "C" void kernel_launch(void* const* d_in, const int* in_sizes, int n_in,
                              void* d_out, int out_size) {
    const float* x          = (const float*)d_in[0];
    const float* proj_W     = (const float*)d_in[1];
    const float* proj_b     = (const float*)d_in[2];
    const float* ln_g       = (const float*)d_in[3];
    const float* ln_b       = (const float*)d_in[4];
    const float* imp_W1     = (const float*)d_in[5];
    const float* imp_b1     = (const float*)d_in[6];
    const float* imp_W2     = (const float*)d_in[7];
    const float* imp_b2     = (const float*)d_in[8];
    const float* gamma      = (const float*)d_in[9];
    const float* modal_bias = (const float*)d_in[10];
    const float* constraint = (const float*)d_in[11];
    float* out = (float*)d_out;

    k_prep<<<GEMM_BLOCKS + 384, 256>>>(x, proj_W, imp_W1, imp_W2);
    k_post<<<NM * NB, 256>>>(proj_b, ln_g, ln_b, imp_b1, imp_b2);
    k_pass<<<NM * ND / 4, 256>>>(modal_bias, constraint);
    k_final<<<NB, ND>>>(gamma, out);
}

// round 7
// speedup vs baseline: 5.8286x; 1.2304x over previous
#include <cuda_runtime.h>
#include <cuda_bf16.h>

#define NM 3
#define NB 64
#define ND 512
#define NDH 128
#define INV_SCALE 0.04419417382415922f   // 1/sqrt(512)
#define INV_HIST_B 0.003125f             // 1/(64*5)
#define LOG2E 1.4426950408889634f
#define SPLITK 8
#define KB (ND / SPLITK)                 // 64 k per gemm block

typedef unsigned long long ull;

// ---------------- scratch (static device globals; no allocation) ----------------
__device__ __align__(16) float g_pp [SPLITK * NM * NB * ND];  // split-k partials
__device__ __align__(16) float g_W1t[NM * ND * NDH];          // imp_W1^T: [i][k][dh]
__device__ __align__(16) float g_W2t[NM * NDH * ND];          // imp_W2^T: [i][kh][d]
__device__ __align__(16) float g_wf [NM * NB * ND];
__device__ float g_rowsum[NM * NB];
__device__ __align__(16) float g_att1[NM * NB * ND];
__device__ __align__(16) float g_att2[NM * NB * ND];
__device__ int g_cnt[NM];   // fan-in counters; reset by k_final each run (init 0)

// ---------------- packed f32x2 helpers ----------------
__device__ __forceinline__ ull pk2(float lo, float hi) {
    ull r; asm("mov.b64 %0, {%1, %2};" : "=l"(r) : "f"(lo), "f"(hi)); return r;
}
__device__ __forceinline__ void upk2(ull v, float& lo, float& hi) {
    asm("mov.b64 {%0, %1}, %2;" : "=f"(lo), "=f"(hi) : "l"(v));
}
__device__ __forceinline__ ull mul2(ull a, ull b) {
    ull r; asm("mul.rn.f32x2 %0, %1, %2;" : "=l"(r) : "l"(a), "l"(b)); return r;
}
__device__ __forceinline__ ull add2(ull a, ull b) {
    ull r; asm("add.rn.f32x2 %0, %1, %2;" : "=l"(r) : "l"(a), "l"(b)); return r;
}
__device__ __forceinline__ ull fma2(ull a, ull b, ull c) {
    ull r; asm("fma.rn.f32x2 %0, %1, %2, %3;" : "=l"(r) : "l"(a), "l"(b), "l"(c)); return r;
}
__device__ __forceinline__ float ex2f(float x) {
    float r; asm("ex2.approx.ftz.f32 %0, %1;" : "=f"(r) : "f"(x)); return r;
}

// ---------------- reduction helpers ----------------
__device__ __forceinline__ float warpRedSum(float v) {
#pragma unroll
    for (int o = 16; o; o >>= 1) v += __shfl_xor_sync(0xffffffffu, v, o);
    return v;
}

// block reduce over 256 threads (8 warps)
__device__ __forceinline__ float blockRed256(float v, float* sred, float* sb,
                                             int lane, int wid) {
    float s = warpRedSum(v);
    if (lane == 0) sred[wid] = s;
    __syncthreads();
    if (wid == 0) {
        float t = (lane < 8) ? sred[lane] : 0.f;
        t = warpRedSum(t);
        if (lane == 0) *sb = t;
    }
    __syncthreads();
    return *sb;
}

// ---------------- K1: fused stage A ----------------
// blocks [0,192):   split-K proj GEMM (ks = b&7, nt = (b>>3)&7, i = b>>6)
// blocks [192,576): W1/W2 transposes (128 per mode)
// blocks [576,768): post (partial-sum + LN + imp1 + imp2 + wf), fan-in on g_cnt
#define KC 16
#define LDS_PAD 68
#define GEMM_BLOCKS (SPLITK * 8 * NM)            // 192
#define TRANS_BLOCKS (64 * 2 * NM)               // 384
#define PROD_PER_MODE (64 + 128)                 // gemm + transpose blocks per mode
__global__ __launch_bounds__(256) void k_fused(
        const float* __restrict__ x, const float* __restrict__ W,
        const float* __restrict__ W1, const float* __restrict__ W2,
        const float* __restrict__ pb, const float* __restrict__ lg,
        const float* __restrict__ lb, const float* __restrict__ b1,
        const float* __restrict__ b2) {
    int bid = blockIdx.x;
    int tid = threadIdx.x;
    if (bid < GEMM_BLOCKS) {
        // ---- proj GEMM ----
        int ks = bid & 7, nt = (bid >> 3) & 7, i = bid >> 6;
        int n0 = nt * 64;
        int tx = tid & 15, ty = tid >> 4;
        int kk = tid & 15, rr = tid >> 4;

        __shared__ float Xs[KC * LDS_PAD];
        __shared__ float Ws[KC * LDS_PAD];

        const float* xb = x + (size_t)i * NB * ND;
        const float* wb = W + (size_t)i * ND * ND + (size_t)n0 * ND;

        float c[4][4];
#pragma unroll
        for (int q = 0; q < 4; q++)
#pragma unroll
            for (int r = 0; r < 4; r++) c[q][r] = 0.f;

#pragma unroll
        for (int cc = 0; cc < KB / KC; cc++) {
            int k0 = ks * KB + cc * KC;
#pragma unroll
            for (int r = 0; r < 4; r++) {
                int b = rr + r * 16;
                Xs[kk * LDS_PAD + b] = xb[(size_t)b * ND + k0 + kk];
                Ws[kk * LDS_PAD + b] = wb[(size_t)b * ND + k0 + kk];
            }
            __syncthreads();
#pragma unroll
            for (int k2 = 0; k2 < KC; k2++) {
                float4 xa = *(const float4*)&Xs[k2 * LDS_PAD + ty * 4];
                float4 wa = *(const float4*)&Ws[k2 * LDS_PAD + tx * 4];
                float xv[4] = {xa.x, xa.y, xa.z, xa.w};
                float wv[4] = {wa.x, wa.y, wa.z, wa.w};
#pragma unroll
                for (int q = 0; q < 4; q++)
#pragma unroll
                    for (int r = 0; r < 4; r++) c[q][r] = fmaf(xv[q], wv[r], c[q][r]);
            }
            __syncthreads();
        }
#pragma unroll
        for (int q = 0; q < 4; q++) {
            int b = ty * 4 + q;
            float4 o = make_float4(c[q][0], c[q][1], c[q][2], c[q][3]);
            *(float4*)&g_pp[((size_t)(ks * NM * NB) + i * NB + b) * ND + n0 + tx * 4] = o;
        }
        __threadfence();
        __syncthreads();
        if (tid == 0) atomicAdd(&g_cnt[i], 1);
    } else if (bid < GEMM_BLOCKS + TRANS_BLOCKS) {
        // ---- transpose: z < NM -> W1 mode z; else W2 mode z-NM ----
        __shared__ float tile[32][33];
        int idx = bid - GEMM_BLOCKS;
        int t = idx & 63;
        int z = idx >> 6;
        int isW2 = (z >= NM);
        int i = isW2 ? z - NM : z;
        int R = isW2 ? ND : NDH;
        int C = isW2 ? NDH : ND;
        int c0 = (isW2 ? (t & 3) : (t & 15)) * 32;
        int r0 = (isW2 ? (t >> 2) : (t >> 4)) * 32;
        const float* s = (isW2 ? W2 : W1) + (size_t)i * R * C;
        float* dd = (isW2 ? g_W2t : g_W1t) + (size_t)i * R * C;
        int tx = tid & 31, ty = tid >> 5;
#pragma unroll
        for (int rr = ty; rr < 32; rr += 8)
            tile[rr][tx] = s[(size_t)(r0 + rr) * C + c0 + tx];
        __syncthreads();
#pragma unroll
        for (int cc = ty; cc < 32; cc += 8)
            dd[(size_t)(c0 + cc) * R + r0 + tx] = tile[tx][cc];
        __threadfence();
        __syncthreads();
        if (tid == 0) atomicAdd(&g_cnt[i], 1);
    } else {
        // ---- post: per-(i,b), 256 threads, 2 d per thread ----
        int idx = bid - GEMM_BLOCKS - TRANS_BLOCKS;
        int i = idx >> 6, b = idx & 63;
        int lane = tid & 31, wid = tid >> 5;
        int d0 = tid, d1 = tid + 256;

        __shared__ float proj_s[ND];
        __shared__ float sP[2 * NDH];
        __shared__ float h_s[NDH];
        __shared__ float sred[8];
        __shared__ float sb;

        // fan-in: wait for all producers of this mode
        if (tid == 0) {
            while (atomicAdd(&g_cnt[i], 0) < PROD_PER_MODE) __nanosleep(64);
        }
        __syncthreads();
        __threadfence();

        float acc0 = 0.f, acc1 = 0.f;
#pragma unroll
        for (int s = 0; s < SPLITK; s++) {
            const float* pp = g_pp + ((size_t)(s * NM * NB) + i * NB + b) * ND;
            acc0 += pp[d0];
            acc1 += pp[d1];
        }
        acc0 += pb[i * ND + d0];
        acc1 += pb[i * ND + d1];

        float mu = blockRed256(acc0 + acc1, sred, &sb, lane, wid) * (1.f / ND);
        float dv0 = acc0 - mu, dv1 = acc1 - mu;
        float var = blockRed256(dv0 * dv0 + dv1 * dv1, sred, &sb, lane, wid) * (1.f / ND);
        float rstd = rsqrtf(var + 1e-5f);
        float p0 = fmaxf(dv0 * rstd * lg[i * ND + d0] + lb[i * ND + d0], 0.f);
        float p1 = fmaxf(dv1 * rstd * lg[i * ND + d1] + lb[i * ND + d1], 0.f);
        proj_s[d0] = p0;
        proj_s[d1] = p1;
        __syncthreads();

        // imp1: 128 dh x 2 k-splits of 256, 4 accumulators each
        {
            int dh = tid & 127, k4 = tid >> 7;
            const float* Wt = g_W1t + (size_t)i * ND * NDH + (size_t)(k4 * 256) * NDH + dh;
            const float* ps = proj_s + k4 * 256;
            float a[4] = {0.f, 0.f, 0.f, 0.f};
#pragma unroll 8
            for (int k = 0; k < 256; k += 4) {
                a[0] = fmaf(Wt[(size_t)(k + 0) * NDH], ps[k + 0], a[0]);
                a[1] = fmaf(Wt[(size_t)(k + 1) * NDH], ps[k + 1], a[1]);
                a[2] = fmaf(Wt[(size_t)(k + 2) * NDH], ps[k + 2], a[2]);
                a[3] = fmaf(Wt[(size_t)(k + 3) * NDH], ps[k + 3], a[3]);
            }
            sP[k4 * NDH + dh] = (a[0] + a[1]) + (a[2] + a[3]);
        }
        __syncthreads();
        if (tid < NDH) {
            float hs = sP[tid] + sP[NDH + tid] + b1[i * NDH + tid];
            h_s[tid] = fmaxf(hs, 0.f);
        }
        __syncthreads();

        // imp2: both d's, 4 accumulators each
        {
            const float* W2t = g_W2t + (size_t)i * NDH * ND;
            float c0[4] = {0.f, 0.f, 0.f, 0.f};
            float c1[4] = {0.f, 0.f, 0.f, 0.f};
#pragma unroll 4
            for (int kh = 0; kh < NDH; kh += 4) {
#pragma unroll
                for (int j = 0; j < 4; j++) {
                    float h = h_s[kh + j];
                    c0[j] = fmaf(W2t[(size_t)(kh + j) * ND + d0], h, c0[j]);
                    c1[j] = fmaf(W2t[(size_t)(kh + j) * ND + d1], h, c1[j]);
                }
            }
            float a20 = (c0[0] + c0[1]) + (c0[2] + c0[3]) + b2[i * ND + d0];
            float a21 = (c1[0] + c1[1]) + (c1[2] + c1[3]) + b2[i * ND + d1];
            float cw0 = 1.f / (1.f + __expf(-a20));
            float cw1 = 1.f / (1.f + __expf(-a21));
            float wf0 = p0 * cw0, wf1 = p1 * cw1;
            float* wfo = g_wf + ((size_t)i * NB + b) * ND;
            wfo[d0] = wf0;
            wfo[d1] = wf1;
            float rs = blockRed256(wf0 + wf1, sred, &sb, lane, wid);
            if (tid == 0) g_rowsum[i * NB + b] = rs;
        }
    }
}

// ---------------- K2: fused pass1+pass2 ----------------
__global__ __launch_bounds__(256, 3) void k_pass(const float* __restrict__ modal_bias,
                                                 const float* __restrict__ constraint) {
    int i = blockIdx.x >> 7;
    int db = (blockIdx.x & 127) << 2;
    int tid = threadIdx.x, lane = tid & 31, wid = tid >> 5;
    int dl = wid >> 1, h = wid & 1;
    int d = db + dl;
    int j1 = (i == 0) ? 1 : 0;
    int j2 = (i == 2) ? 1 : 2;
    float c = constraint[i];
    float bias1 = modal_bias[i * NM + j1];
    float bias2 = modal_bias[i * NM + j2];
    float B = 0.8f * c * LOG2E;          // pass-A clamp half-width (pre-scaled by 0.8)
    float CL = c * LOG2E;                // clip bound in ex2 domain
    ull C02 = pk2(0.2f, 0.2f);
    ull C08 = pk2(0.8f, 0.8f);
    ull NB2 = pk2(-B, -B);
    ull PB2 = pk2(B, B);
    ull CL2 = pk2(CL, CL);
    ull NCL2 = pk2(-CL, -CL);
    ull IHB2 = pk2(INV_HIST_B, INV_HIST_B);

    const float* wfi = g_wf + (size_t)i * NB * ND;
    const float* wf1 = g_wf + (size_t)j1 * NB * ND;
    const float* wf2 = g_wf + (size_t)j2 * NB * ND;
    const float* rs1 = g_rowsum + j1 * NB;
    const float* rs2 = g_rowsum + j2 * NB;

    __shared__ ull sH[8][256];

    // a (pre-scaled into ex2 domain) for this warp's 32 batch rows, one per lane
    float aL_r = wfi[(size_t)(h * 32 + lane) * ND + d] * (INV_SCALE * LOG2E);

    ull H2[8];
#pragma unroll
    for (int kp = 0; kp < 8; kp++) H2[kp] = 0ull;

    // ---- pass A (hist = 0), pair (i, j1): f = 0.2*cur + clamp(0.8*cur, -B, B) ----
    for (int bb = 0; bb < 32; bb++) {
        int b = h * 32 + bb;
        float a = __shfl_sync(0xffffffffu, aL_r, bb);
        ull a2 = pk2(a, a);
        const ulonglong2* vr = (const ulonglong2*)(wf1 + (size_t)b * ND);
        ulonglong2 q0 = vr[lane], q1 = vr[32 + lane], q2 = vr[64 + lane], q3 = vr[96 + lane];
        ull vv[8] = {q0.x, q0.y, q1.x, q1.y, q2.x, q2.y, q3.x, q3.y};
        ull ps2 = 0ull, pd2 = 0ull;
#pragma unroll
        for (int kp = 0; kp < 8; kp++) {
            ull cur2 = mul2(a2, vv[kp]);
            ull u2 = fma2(cur2, C02, NB2);
            ull w2 = fma2(cur2, C02, PB2);
            float x0, x1, u0, u1, w0, w1;
            upk2(cur2, x0, x1); upk2(u2, u0, u1); upk2(w2, w0, w1);
            float f0 = fminf(fmaxf(x0, u0), w0);
            float f1 = fminf(fmaxf(x1, u1), w1);
            H2[kp] = add2(H2[kp], pk2(f0, f1));
            ull pp = pk2(ex2f(f0), ex2f(f1));
            ps2 = add2(ps2, pp);
            pd2 = fma2(pp, vv[kp], pd2);
        }
        float s0, s1, dd0, dd1;
        upk2(ps2, s0, s1); upk2(pd2, dd0, dd1);
        float ps = warpRedSum(s0 + s1);
        float pd = warpRedSum(dd0 + dd1);
        if (lane == 0)
            g_att1[((size_t)i * NB + b) * ND + d] = pd / ps + bias1 * rs1[b];
    }

    // exchange history partials between the two half-batch warps of this d
#pragma unroll
    for (int kp = 0; kp < 8; kp++) sH[wid][kp * 32 + lane] = H2[kp];
    __syncthreads();
    // pass-B bounds: f = 0.2*cur + clamp(0.8*cur, 0.8*(H-C), 0.8*(H+C))
    ull lo2[8], hi2[8];
#pragma unroll
    for (int kp = 0; kp < 8; kp++) {
        ull hsum = add2(sH[dl * 2][kp * 32 + lane], sH[dl * 2 + 1][kp * 32 + lane]);
        ull hist2 = mul2(hsum, IHB2);
        lo2[kp] = mul2(add2(hist2, NCL2), C08);
        hi2[kp] = mul2(add2(hist2, CL2), C08);
    }

    // ---- pass B, pair (i, j2) ----
    for (int bb = 0; bb < 32; bb++) {
        int b = h * 32 + bb;
        float a = __shfl_sync(0xffffffffu, aL_r, bb);
        ull a2 = pk2(a, a);
        const ulonglong2* vr = (const ulonglong2*)(wf2 + (size_t)b * ND);
        ulonglong2 q0 = vr[lane], q1 = vr[32 + lane], q2 = vr[64 + lane], q3 = vr[96 + lane];
        ull vv[8] = {q0.x, q0.y, q1.x, q1.y, q2.x, q2.y, q3.x, q3.y};
        ull ps2 = 0ull, pd2 = 0ull;
#pragma unroll
        for (int kp = 0; kp < 8; kp++) {
            ull cur2 = mul2(a2, vv[kp]);
            ull s2 = mul2(cur2, C08);
            float s0, s1, l0, l1, hh0, hh1;
            upk2(s2, s0, s1);
            upk2(lo2[kp], l0, l1);
            upk2(hi2[kp], hh0, hh1);
            float cl0 = fminf(fmaxf(s0, l0), hh0);
            float cl1 = fminf(fmaxf(s1, l1), hh1);
            ull f2 = fma2(cur2, C02, pk2(cl0, cl1));
            float f0, f1;
            upk2(f2, f0, f1);
            ull pp = pk2(ex2f(f0), ex2f(f1));
            ps2 = add2(ps2, pp);
            pd2 = fma2(pp, vv[kp], pd2);
        }
        float s0, s1, dd0, dd1;
        upk2(ps2, s0, s1); upk2(pd2, dd0, dd1);
        float ps = warpRedSum(s0 + s1);
        float pd = warpRedSum(dd0 + dd1);
        if (lane == 0)
            g_att2[((size_t)i * NB + b) * ND + d] = pd / ps + bias2 * rs2[b];
    }
}

// ---------------- K3: fuse + attention weights + counter reset ----------------
__global__ __launch_bounds__(128) void k_final(const float* __restrict__ gamma,
                                               float* __restrict__ out) {
    int idx = blockIdx.x * 128 + threadIdx.x;   // [0, 32768)
    int b = idx >> 9, d = idx & 511;
    if (idx < NM) g_cnt[idx] = 0;               // reset fan-in for next replay
    float acc = 0.f;
#pragma unroll
    for (int i = 0; i < NM; i++) {
        int j1 = (i == 0) ? 1 : 0;
        int j2 = (i == 2) ? 1 : 2;
        float g1 = 1.f / (1.f + __expf(-gamma[i * NM + j1]));
        float g2 = 1.f / (1.f + __expf(-gamma[i * NM + j2]));
        int o = ((i << 6) + b) * ND + d;
        acc += g_wf[o] + 0.5f * (g1 * g_att1[o] + g2 * g_att2[o]);
    }
    out[b * ND + d] = acc * (1.0f / 3.0f);
    if (idx == 0) {
        float sc[NM];
        float mx = -3.4e38f;
#pragma unroll
        for (int i = 0; i < NM; i++) {
            int j1 = (i == 0) ? 1 : 0;
            int j2 = (i == 2) ? 1 : 2;
            float g1 = 1.f / (1.f + __expf(-gamma[i * NM + j1]));
            float g2 = 1.f / (1.f + __expf(-gamma[i * NM + j2]));
            sc[i] = 0.5f * (g1 + g2);
            mx = fmaxf(mx, sc[i]);
        }
        float s = 0.f;
#pragma unroll
        for (int i = 0; i < NM; i++) { sc[i] = __expf(sc[i] - mx); s += sc[i]; }
#pragma unroll
        for (int i = 0; i < NM; i++) out[NB * ND + i] = sc[i] / s;
    }
}

extern "C" void kernel_launch(void* const* d_in, const int* in_sizes, int n_in,
                              void* d_out, int out_size) {
    const float* x          = (const float*)d_in[0];
    const float* proj_W     = (const float*)d_in[1];
    const float* proj_b     = (const float*)d_in[2];
    const float* ln_g       = (const float*)d_in[3];
    const float* ln_b       = (const float*)d_in[4];
    const float* imp_W1     = (const float*)d_in[5];
    const float* imp_b1     = (const float*)d_in[6];
    const float* imp_W2     = (const float*)d_in[7];
    const float* imp_b2     = (const float*)d_in[8];
    const float* gamma      = (const float*)d_in[9];
    const float* modal_bias = (const float*)d_in[10];
    const float* constraint = (const float*)d_in[11];
    float* out = (float*)d_out;

    k_fused<<<GEMM_BLOCKS + TRANS_BLOCKS + NM * NB, 256>>>(
        x, proj_W, imp_W1, imp_W2, proj_b, ln_g, ln_b, imp_b1, imp_b2);
    k_pass<<<NM * ND / 4, 256>>>(modal_bias, constraint);
    k_final<<<NB * ND / 128, 128>>>(gamma, out);
}